// round 6
// baseline (speedup 1.0000x reference)
#include <cuda_runtime.h>
#include <mma.h>
#include <cstdint>
#include <cstddef>

using namespace nvcuda;

#define B_ 32
#define L_ 512
#define D_ 768
#define H_ 12
#define SSTR 516

// ---------------- scratch ----------------
__device__ float g_qh[(size_t)B_*L_*D_];
__device__ float g_kh[(size_t)B_*L_*D_];
__device__ float g_vh[(size_t)B_*L_*D_];
__device__ float g_qt[(size_t)B_*L_*D_];
__device__ float g_ctx[(size_t)B_*L_*D_];
__device__ float g_x[(size_t)B_*L_*D_];
__device__ float g_sw[(size_t)B_*L_*72];
__device__ float g_qc[(size_t)B_*L_*D_];
__device__ float g_kc[(size_t)B_*L_*D_];
__device__ float g_vc[(size_t)B_*L_*D_];
__device__ float g_Wqc[D_*D_];
__device__ float g_Wkc[D_*D_];
__device__ float g_Wvc[D_*D_];
__device__ float g_Wfcc[D_*D_];
__device__ float g_Wcc[D_*72];
__device__ int   g_mask_mode;

// ---------------- cp.async helpers ----------------
__device__ __forceinline__ void cp16(void* s, const void* g) {
    unsigned a = (unsigned)__cvta_generic_to_shared(s);
    asm volatile("cp.async.cg.shared.global [%0], [%1], 16;\n" :: "r"(a), "l"(g));
}
__device__ __forceinline__ void cp16z(void* s, const void* g, int sb) {
    unsigned a = (unsigned)__cvta_generic_to_shared(s);
    asm volatile("cp.async.cg.shared.global [%0], [%1], 16, %2;\n" :: "r"(a), "l"(g), "r"(sb));
}
#define CP_COMMIT() asm volatile("cp.async.commit_group;\n")

// ---------------- mask dtype detection ----------------
__global__ void detect_mask_k(const unsigned int* __restrict__ w) {
    __shared__ int sF, sO;
    if (threadIdx.x == 0) { sF = 0; sO = 0; }
    __syncthreads();
    int f = 0, o = 0;
    for (int i = threadIdx.x; i < 4096; i += 256) {
        unsigned v = w[i];
        if (v == 0x3F800000u) f = 1;
        else if (v > 1u) o = 1;
    }
    if (f) atomicOr(&sF, 1);
    if (o) atomicOr(&sO, 1);
    __syncthreads();
    if (threadIdx.x == 0) g_mask_mode = sF ? 1 : (sO ? 2 : 0);
}

__device__ __forceinline__ int is_masked(const void* mp, int idx, int mode) {
    if (mode == 2) return ((const unsigned char*)mp)[idx] != 0;
    if (mode == 1) return ((const float*)mp)[idx] != 0.0f;
    return ((const int*)mp)[idx] != 0;
}

// ---------------- tf32 pre-rounding of operands ----------------
struct ConvP { const float* src[8]; float* dst[8]; int n[8]; };
__global__ void conv_k(ConvP p) {
    int s = blockIdx.y;
    int i = (blockIdx.x * 256 + threadIdx.x) * 4;
    if (i >= p.n[s]) return;
    float4 v = *(const float4*)(p.src[s] + i);
    v.x = wmma::__float_to_tf32(v.x); v.y = wmma::__float_to_tf32(v.y);
    v.z = wmma::__float_to_tf32(v.z); v.w = wmma::__float_to_tf32(v.w);
    *(float4*)(p.dst[s] + i) = v;
}

// ---------------- qt = tf32(q + txt) ----------------
__global__ void add_txt_k(const float* __restrict__ q, const float* __restrict__ txt) {
    size_t idx = (size_t)blockIdx.x * 256 + threadIdx.x;
    if (idx >= (size_t)B_*L_*D_) return;
    int b = (int)(idx / ((size_t)L_*D_));
    int c = (int)(idx % D_);
    g_qt[idx] = wmma::__float_to_tf32(q[idx] + txt[b*D_ + c]);
}

// ---------------- pipelined tf32 GEMM (operands pre-rounded) ----------------
struct GemmP {
    const float* A[3]; const float* Bw[3]; const float* bias[3]; float* C[3];
    const float* resid;
    int N, K, lda, ldb, ldc, roundOut;
};

template<int NF>
__global__ __launch_bounds__(256) void gemm_k(GemmP p)
{
    constexpr int BN = 32*NF;
    constexpr int ASTR = 36, BSTR = BN + 4;
    constexpr int ASZ = 128*ASTR, BSZ = 32*BSTR;
    extern __shared__ float dsm[];
    float* sA = dsm;
    float* sB = dsm + 2*ASZ;
    float* stag = sB + 2*BSZ;

    int set = blockIdx.z;
    const float* A  = p.A[set];
    const float* Bw = p.Bw[set];
    const float* bias = p.bias[set];
    float* C = p.C[set];
    int m0 = blockIdx.x*128, n0 = blockIdx.y*BN;
    int tid = threadIdx.x, lane = tid&31, wid = tid>>5;
    int wm = wid>>1, wn = wid&1;

    auto prefetch = [&](int kt, int buf) {
        float* dA = sA + buf*ASZ; float* dB = sB + buf*BSZ;
        #pragma unroll
        for (int i=0;i<4;i++) {
            int idx = tid + i*256;
            int r = idx>>3, c = (idx&7)*4;
            cp16(dA + r*ASTR + c, A + (size_t)(m0+r)*p.lda + kt + c);
        }
        #pragma unroll
        for (int i=0;i<NF;i++) {
            int idx = tid + i*256;
            int r = idx/(BN/4), c = (idx%(BN/4))*4;
            int sb = (n0 + c + 4 <= p.N) ? 16 : 0;
            cp16z(dB + r*BSTR + c, Bw + (size_t)(kt+r)*p.ldb + n0 + c, sb);
        }
        CP_COMMIT();
    };

    wmma::fragment<wmma::accumulator,16,16,8,float> acc[2][NF];
    #pragma unroll
    for (int i=0;i<2;i++)
    #pragma unroll
    for (int j=0;j<NF;j++) wmma::fill_fragment(acc[i][j], 0.f);

    prefetch(0, 0);
    int nk = p.K/32;
    for (int k=0;k<nk;k++) {
        int cur = k&1;
        if (k+1 < nk) {
            prefetch((k+1)*32, cur^1);
            asm volatile("cp.async.wait_group 1;\n");
        } else {
            asm volatile("cp.async.wait_group 0;\n");
        }
        __syncthreads();
        const float* cA = sA + cur*ASZ;
        const float* cB = sB + cur*BSZ;
        #pragma unroll
        for (int kk=0;kk<32;kk+=8) {
            wmma::fragment<wmma::matrix_a,16,16,8,wmma::precision::tf32,wmma::row_major> af[2];
            #pragma unroll
            for (int i=0;i<2;i++)
                wmma::load_matrix_sync(af[i], cA + (wm*32+16*i)*ASTR + kk, ASTR);
            wmma::fragment<wmma::matrix_b,16,16,8,wmma::precision::tf32,wmma::row_major> bf[NF];
            #pragma unroll
            for (int j=0;j<NF;j++)
                wmma::load_matrix_sync(bf[j], cB + kk*BSTR + wn*NF*16 + 16*j, BSTR);
            #pragma unroll
            for (int i=0;i<2;i++)
            #pragma unroll
            for (int j=0;j<NF;j++) wmma::mma_sync(acc[i][j], af[i], bf[j], acc[i][j]);
        }
        __syncthreads();
    }

    float* st = stag + wid*320;
    #pragma unroll
    for (int i=0;i<2;i++)
    #pragma unroll
    for (int j=0;j<NF;j++) {
        wmma::store_matrix_sync(st, acc[i][j], 20, wmma::mem_row_major);
        __syncwarp();
        int mb = m0 + wm*32 + i*16;
        int nb = n0 + wn*NF*16 + j*16;
        int r = lane>>1, c0 = (lane&1)*8;
        const float* src = st + r*20 + c0;
        float* dst = C + (size_t)(mb+r)*p.ldc + nb + c0;
        if (nb + 16 <= p.N) {
            float4 v0 = *(const float4*)(src);
            float4 v1 = *(const float4*)(src+4);
            if (bias) {
                float4 b0 = *(const float4*)(bias + nb + c0);
                float4 b1 = *(const float4*)(bias + nb + c0 + 4);
                v0.x+=b0.x; v0.y+=b0.y; v0.z+=b0.z; v0.w+=b0.w;
                v1.x+=b1.x; v1.y+=b1.y; v1.z+=b1.z; v1.w+=b1.w;
            }
            if (p.resid) {
                const float* rp = p.resid + (size_t)(mb+r)*p.ldc + nb + c0;
                float4 r0 = *(const float4*)(rp);
                float4 r1 = *(const float4*)(rp+4);
                v0.x+=r0.x; v0.y+=r0.y; v0.z+=r0.z; v0.w+=r0.w;
                v1.x+=r1.x; v1.y+=r1.y; v1.z+=r1.z; v1.w+=r1.w;
            }
            if (p.roundOut) {
                v0.x=wmma::__float_to_tf32(v0.x); v0.y=wmma::__float_to_tf32(v0.y);
                v0.z=wmma::__float_to_tf32(v0.z); v0.w=wmma::__float_to_tf32(v0.w);
                v1.x=wmma::__float_to_tf32(v1.x); v1.y=wmma::__float_to_tf32(v1.y);
                v1.z=wmma::__float_to_tf32(v1.z); v1.w=wmma::__float_to_tf32(v1.w);
            }
            *(float4*)(dst) = v0;
            *(float4*)(dst+4) = v1;
        } else {
            #pragma unroll
            for (int t=0;t<8;t++) {
                int n = nb + c0 + t;
                if (n < p.N) {
                    float v = src[t];
                    if (bias) v += bias[n];
                    if (p.resid) v += p.resid[(size_t)(mb+r)*p.ldc + n];
                    dst[t] = v;
                }
            }
        }
        __syncwarp();
    }
}

// ---------------- fused attention megakernel ----------------
// one block = (b, h, 64 query rows); S tile resident in smem
__global__ __launch_bounds__(256) void attn_k(
    const float* __restrict__ ploc, const void* __restrict__ maskp,
    float* __restrict__ P)
{
    extern __shared__ float dsm[];
    float* sS = dsm;                       // 64 x SSTR
    float* sQ = dsm + 64*SSTR;             // 64 x 72
    float* sT = sQ + 64*72;                // 64 x 72
    unsigned char* smask = (unsigned char*)(sT + 64*72);   // 512

    int h = blockIdx.x % H_, lt = blockIdx.x / H_, b = blockIdx.y;
    int l0 = lt*64;
    int tid = threadIdx.x, lane = tid&31, wid = tid>>5;
    int wm = wid>>1, wn = wid&1;
    int mode = g_mask_mode;

    const float* Qb = g_qh + ((size_t)(b*L_+l0))*D_ + h*64;
    const float* Kb = g_kh + ((size_t)b*L_)*D_ + h*64;
    const float* Vb = g_vh + ((size_t)b*L_)*D_ + h*64;

    #pragma unroll
    for (int i=0;i<4;i++) {
        int idx = tid + i*256; int r = idx>>4, c = (idx&15)*4;
        *(float4*)(sQ + r*72 + c) = *(const float4*)(Qb + (size_t)r*D_ + c);
    }
    for (int i=tid;i<L_;i+=256)
        smask[i] = (unsigned char)is_masked(maskp, b*L_ + i, mode);

    float4 pre[4];
    auto loadT = [&](const float* base, int kt) {
        #pragma unroll
        for (int i=0;i<4;i++) {
            int idx = tid + i*256; int r = idx>>4, c = (idx&15)*4;
            pre[i] = *(const float4*)(base + (size_t)(kt*64+r)*D_ + c);
        }
    };
    auto storeT = [&]() {
        #pragma unroll
        for (int i=0;i<4;i++) {
            int idx = tid + i*256; int r = idx>>4, c = (idx&15)*4;
            *(float4*)(sT + r*72 + c) = pre[i];
        }
    };

    // -------- phase 1: S = 0.125 * Q @ K^T --------
    loadT(Kb, 0);
    for (int kt=0; kt<8; kt++) {
        __syncthreads();
        storeT();
        __syncthreads();
        if (kt < 7) loadT(Kb, kt+1);
        wmma::fragment<wmma::accumulator,16,16,8,float> acc[2];
        wmma::fill_fragment(acc[0], 0.f);
        wmma::fill_fragment(acc[1], 0.f);
        #pragma unroll
        for (int kk=0;kk<64;kk+=8) {
            wmma::fragment<wmma::matrix_a,16,16,8,wmma::precision::tf32,wmma::row_major> a;
            wmma::load_matrix_sync(a, sQ + (wm*16)*72 + kk, 72);
            #pragma unroll
            for (int j=0;j<2;j++) {
                wmma::fragment<wmma::matrix_b,16,16,8,wmma::precision::tf32,wmma::col_major> bf;
                wmma::load_matrix_sync(bf, sT + (wn*32+16*j)*72 + kk, 72);
                wmma::mma_sync(acc[j], a, bf, acc[j]);
            }
        }
        #pragma unroll
        for (int j=0;j<2;j++) {
            #pragma unroll
            for (int t=0;t<acc[j].num_elements;t++) acc[j].x[t] *= 0.125f;
            wmma::store_matrix_sync(sS + (wm*16)*SSTR + kt*64 + wn*32 + 16*j,
                                    acc[j], SSTR, wmma::mem_row_major);
        }
    }
    __syncthreads();

    // -------- phase 2: spatial gate + softmax (warp per 8 rows) --------
    for (int rr=0; rr<8; rr++) {
        int r = wid*8 + rr; int l = l0 + r;
        const float* swp = g_sw + ((size_t)(b*L_+l))*72 + h*6;
        float c0=swp[0], c1=swp[1], c2=swp[2], c3=swp[3], c4=swp[4], c5=swp[5];
        const float* plp = ploc + ((size_t)(b*L_ + l))*L_*5;
        float xs[16]; float mx = -INFINITY;
        #pragma unroll 4
        for (int j=0;j<16;j++) {
            int t = lane + j*32;
            float sv = sS[r*SSTR + t];
            const float* pp = plp + t*5;
            float loc = c0 + c1*pp[0] + c2*pp[1] + c3*pp[2] + c4*pp[3] + c5*pp[4];
            float x;
            if (smask[t]) x = -INFINITY;
            else {
                float sg = 1.f/(1.f + __expf(-loc));
                x = sv + __logf(fmaxf(sg, 1e-6f));
            }
            xs[j] = x; mx = fmaxf(mx, x);
        }
        #pragma unroll
        for (int o=16;o;o>>=1) mx = fmaxf(mx, __shfl_xor_sync(~0u, mx, o));
        float s = 0.f;
        #pragma unroll
        for (int j=0;j<16;j++) {
            int t = lane + j*32;
            float e = smask[t] ? 0.f : __expf(xs[j] - mx);
            xs[j] = e; s += e;
        }
        #pragma unroll
        for (int o=16;o;o>>=1) s += __shfl_xor_sync(~0u, s, o);
        float inv = 1.f/s;
        #pragma unroll
        for (int j=0;j<16;j++) sS[r*SSTR + lane + j*32] = xs[j]*inv;
    }
    __syncthreads();

    // -------- phase 3: write P (fp32 exact), round sS to tf32 in place --------
    float* Pb = P + ((size_t)((b*H_+h)*L_ + l0))*L_;
    #pragma unroll
    for (int i=0;i<32;i++) {
        int idx = tid + i*256; int r = idx>>7, c = (idx&127)*4;
        float4 v = *(float4*)(sS + r*SSTR + c);
        *(float4*)(Pb + (size_t)r*L_ + c) = v;
        v.x = wmma::__float_to_tf32(v.x); v.y = wmma::__float_to_tf32(v.y);
        v.z = wmma::__float_to_tf32(v.z); v.w = wmma::__float_to_tf32(v.w);
        *(float4*)(sS + r*SSTR + c) = v;
    }

    // -------- phase 4: ctx = P @ V --------
    wmma::fragment<wmma::accumulator,16,16,8,float> o2[2];
    wmma::fill_fragment(o2[0], 0.f);
    wmma::fill_fragment(o2[1], 0.f);
    loadT(Vb, 0);
    for (int kt=0; kt<8; kt++) {
        __syncthreads();
        storeT();
        __syncthreads();
        if (kt < 7) loadT(Vb, kt+1);
        #pragma unroll
        for (int kk=0;kk<64;kk+=8) {
            wmma::fragment<wmma::matrix_a,16,16,8,wmma::precision::tf32,wmma::row_major> a;
            wmma::load_matrix_sync(a, sS + (wm*16)*SSTR + kt*64 + kk, SSTR);
            #pragma unroll
            for (int j=0;j<2;j++) {
                wmma::fragment<wmma::matrix_b,16,16,8,wmma::precision::tf32,wmma::row_major> bf;
                wmma::load_matrix_sync(bf, sT + kk*72 + wn*32 + 16*j, 72);
                wmma::mma_sync(o2[j], a, bf, o2[j]);
            }
        }
    }
    __syncthreads();
    #pragma unroll
    for (int j=0;j<2;j++) {
        #pragma unroll
        for (int t=0;t<o2[j].num_elements;t++)
            o2[j].x[t] = wmma::__float_to_tf32(o2[j].x[t]);
        wmma::store_matrix_sync(sQ + (wm*16)*72 + wn*32 + 16*j, o2[j], 72,
                                wmma::mem_row_major);
    }
    __syncthreads();
    float* Cb = g_ctx + ((size_t)(b*L_+l0))*D_ + h*64;
    #pragma unroll
    for (int i=0;i<4;i++) {
        int idx = tid + i*256; int r = idx>>4, c = (idx&15)*4;
        *(float4*)(Cb + (size_t)r*D_ + c) = *(float4*)(sQ + r*72 + c);
    }
}

// ---------------- LayerNorm ----------------
__global__ __launch_bounds__(256) void ln_k(
    const float* __restrict__ sc, const float* __restrict__ bs, float* __restrict__ Y)
{
    int row = blockIdx.x;
    const float* x = g_x + (size_t)row*D_;
    float* y = Y + (size_t)row*D_;
    __shared__ float r1[8], r2[8];
    int tid = threadIdx.x;
    float v0=x[tid], v1=x[tid+256], v2=x[tid+512];
    float s = v0+v1+v2, q = v0*v0+v1*v1+v2*v2;
    #pragma unroll
    for (int o=16;o;o>>=1) {
        s += __shfl_xor_sync(~0u, s, o);
        q += __shfl_xor_sync(~0u, q, o);
    }
    if ((tid&31)==0) { r1[tid>>5]=s; r2[tid>>5]=q; }
    __syncthreads();
    s = r1[0]+r1[1]+r1[2]+r1[3]+r1[4]+r1[5]+r1[6]+r1[7];
    q = r2[0]+r2[1]+r2[2]+r2[3]+r2[4]+r2[5]+r2[6]+r2[7];
    float mu = s * (1.f/D_);
    float var = q * (1.f/D_) - mu*mu;
    float r = rsqrtf(var + 1e-5f);
    y[tid]     = (v0-mu)*r*sc[tid]     + bs[tid];
    y[tid+256] = (v1-mu)*r*sc[tid+256] + bs[tid+256];
    y[tid+512] = (v2-mu)*r*sc[tid+512] + bs[tid+512];
}

// ---------------- host ----------------
extern "C" void kernel_launch(void* const* d_in, const int* in_sizes, int n_in,
                              void* d_out, int out_size) {
    const float* q    = (const float*)d_in[0];
    const float* k    = (const float*)d_in[1];
    const float* v    = (const float*)d_in[2];
    const float* ploc = (const float*)d_in[3];
    const float* txt  = (const float*)d_in[4];
    const void*  mask = d_in[5];
    const float* Wq = (const float*)d_in[6],  *bq = (const float*)d_in[7];
    const float* Wk = (const float*)d_in[8],  *bk = (const float*)d_in[9];
    const float* Wv = (const float*)d_in[10], *bv = (const float*)d_in[11];
    const float* Wfc= (const float*)d_in[12], *bfc= (const float*)d_in[13];
    const float* Wc = (const float*)d_in[14], *bc = (const float*)d_in[15];
    const float* lns= (const float*)d_in[16], *lnb= (const float*)d_in[17];

    float* y = (float*)d_out;
    float* P = y + (size_t)B_*L_*D_;

    void *p0,*p1,*p2,*p3,*p4,*p5,*p6,*p7,*p8,*p9,*pa,*pb,*pc,*pd;
    cudaGetSymbolAddress(&p0, g_qh);  cudaGetSymbolAddress(&p1, g_kh);
    cudaGetSymbolAddress(&p2, g_vh);  cudaGetSymbolAddress(&p3, g_qt);
    cudaGetSymbolAddress(&p4, g_ctx); cudaGetSymbolAddress(&p5, g_x);
    cudaGetSymbolAddress(&p6, g_sw);  cudaGetSymbolAddress(&p7, g_qc);
    cudaGetSymbolAddress(&p8, g_kc);  cudaGetSymbolAddress(&p9, g_vc);
    cudaGetSymbolAddress(&pa, g_Wqc); cudaGetSymbolAddress(&pb, g_Wkc);
    cudaGetSymbolAddress(&pc, g_Wvc); cudaGetSymbolAddress(&pd, g_Wfcc);
    void* pe; cudaGetSymbolAddress(&pe, g_Wcc);
    float *qh=(float*)p0, *kh=(float*)p1, *vh=(float*)p2, *qt=(float*)p3;
    float *ctx=(float*)p4, *xx=(float*)p5, *sw=(float*)p6;
    float *qc=(float*)p7, *kc=(float*)p8, *vc=(float*)p9;
    float *Wqc=(float*)pa, *Wkc=(float*)pb, *Wvc=(float*)pc, *Wfcc=(float*)pd, *Wcc=(float*)pe;

    const int M = B_*L_;
    const int NQ = M*D_, NW = D_*D_, NWC = D_*72;

    constexpr int GS4 = (2*(128*36) + 2*(32*132) + 8*320) * 4;
    constexpr int GS2 = (2*(128*36) + 2*(32*68)  + 8*320) * 4;
    constexpr int AS  = (64*SSTR + 2*64*72) * 4 + 512;
    cudaFuncSetAttribute(gemm_k<4>, cudaFuncAttributeMaxDynamicSharedMemorySize, GS4);
    cudaFuncSetAttribute(gemm_k<2>, cudaFuncAttributeMaxDynamicSharedMemorySize, GS2);
    cudaFuncSetAttribute(attn_k,    cudaFuncAttributeMaxDynamicSharedMemorySize, AS);

    detect_mask_k<<<1,256>>>((const unsigned int*)mask);

    { // tf32 pre-rounding: q,k,v copies + 5 weights
        ConvP cp{};
        cp.src[0]=q;   cp.dst[0]=qc;   cp.n[0]=NQ;
        cp.src[1]=k;   cp.dst[1]=kc;   cp.n[1]=NQ;
        cp.src[2]=v;   cp.dst[2]=vc;   cp.n[2]=NQ;
        cp.src[3]=Wq;  cp.dst[3]=Wqc;  cp.n[3]=NW;
        cp.src[4]=Wk;  cp.dst[4]=Wkc;  cp.n[4]=NW;
        cp.src[5]=Wv;  cp.dst[5]=Wvc;  cp.n[5]=NW;
        cp.src[6]=Wfc; cp.dst[6]=Wfcc; cp.n[6]=NW;
        cp.src[7]=Wc;  cp.dst[7]=Wcc;  cp.n[7]=NWC;
        conv_k<<<dim3(NQ/1024, 8), 256>>>(cp);
    }
    add_txt_k<<<(NQ + 255)/256, 256>>>(q, txt);

    { // Q/K/V projections (rounded outputs for attention operands)
        GemmP g{};
        g.A[0]=qc; g.A[1]=kc; g.A[2]=vc;
        g.Bw[0]=Wqc; g.Bw[1]=Wkc; g.Bw[2]=Wvc;
        g.bias[0]=bq; g.bias[1]=bk; g.bias[2]=bv;
        g.C[0]=qh; g.C[1]=kh; g.C[2]=vh;
        g.resid=nullptr; g.N=D_; g.K=D_; g.lda=D_; g.ldb=D_; g.ldc=D_; g.roundOut=1;
        gemm_k<4><<<dim3(M/128, D_/128, 3), 256, GS4>>>(g);
    }
    { // cond: qt @ Wc (fp32 out)
        GemmP g{};
        g.A[0]=qt; g.Bw[0]=Wcc; g.bias[0]=bc; g.C[0]=sw;
        g.resid=nullptr; g.N=72; g.K=D_; g.lda=D_; g.ldb=72; g.ldc=72; g.roundOut=0;
        gemm_k<2><<<dim3(M/128, 2, 1), 256, GS2>>>(g);
    }
    // fused QK^T + gate + softmax + PV
    attn_k<<<dim3((L_/64)*H_, B_), 256, AS>>>(ploc, mask, P);
    { // x = ctx @ Wfc + bfc + q
        GemmP g{};
        g.A[0]=ctx; g.Bw[0]=Wfcc; g.bias[0]=bfc; g.C[0]=xx;
        g.resid=q; g.N=D_; g.K=D_; g.lda=D_; g.ldb=D_; g.ldc=D_; g.roundOut=0;
        gemm_k<4><<<dim3(M/128, D_/128, 1), 256, GS4>>>(g);
    }
    ln_k<<<M, 256>>>(lns, lnb, y);
}

// round 8
// speedup vs baseline: 1.6639x; 1.6639x over previous
#include <cuda_runtime.h>
#include <mma.h>
#include <cstdint>
#include <cstddef>

using namespace nvcuda;

#define B_ 32
#define L_ 512
#define D_ 768
#define H_ 12

// ---------------- scratch ----------------
__device__ float g_qh[(size_t)B_*L_*D_];
__device__ float g_kh[(size_t)B_*L_*D_];
__device__ float g_vh[(size_t)B_*L_*D_];
__device__ float g_qt[(size_t)B_*L_*D_];
__device__ float g_ctx[(size_t)B_*L_*D_];
__device__ float g_x[(size_t)B_*L_*D_];
__device__ float g_sw[(size_t)B_*L_*72];
__device__ float g_qc[(size_t)B_*L_*D_];
__device__ float g_kc[(size_t)B_*L_*D_];
__device__ float g_vc[(size_t)B_*L_*D_];
__device__ float g_Wqc[D_*D_];
__device__ float g_Wkc[D_*D_];
__device__ float g_Wvc[D_*D_];
__device__ float g_Wfcc[D_*D_];
__device__ int   g_mask_mode;

// ---------------- cp.async ----------------
__device__ __forceinline__ void cp16(void* s, const void* g) {
    unsigned a = (unsigned)__cvta_generic_to_shared(s);
    asm volatile("cp.async.cg.shared.global [%0], [%1], 16;\n" :: "r"(a), "l"(g));
}
#define CP_COMMIT() asm volatile("cp.async.commit_group;\n")

// ---------------- mask dtype detection ----------------
__global__ void detect_mask_k(const unsigned int* __restrict__ w) {
    __shared__ int sF, sO;
    if (threadIdx.x == 0) { sF = 0; sO = 0; }
    __syncthreads();
    int f = 0, o = 0;
    for (int i = threadIdx.x; i < 4096; i += 256) {
        unsigned v = w[i];
        if (v == 0x3F800000u) f = 1;
        else if (v > 1u) o = 1;
    }
    if (f) atomicOr(&sF, 1);
    if (o) atomicOr(&sO, 1);
    __syncthreads();
    if (threadIdx.x == 0) g_mask_mode = sF ? 1 : (sO ? 2 : 0);
}

__device__ __forceinline__ int is_masked(const void* mp, int idx, int mode) {
    if (mode == 2) return ((const unsigned char*)mp)[idx] != 0;
    if (mode == 1) return ((const float*)mp)[idx] != 0.0f;
    return ((const int*)mp)[idx] != 0;
}

// ---------------- tf32 RN pre-rounding ----------------
struct ConvP { const float* src[7]; float* dst[7]; int n[7]; };
__global__ void conv_k(ConvP p) {
    int s = blockIdx.y;
    int i = (blockIdx.x * 256 + threadIdx.x) * 4;
    if (i >= p.n[s]) return;
    float4 v = *(const float4*)(p.src[s] + i);
    v.x = wmma::__float_to_tf32(v.x); v.y = wmma::__float_to_tf32(v.y);
    v.z = wmma::__float_to_tf32(v.z); v.w = wmma::__float_to_tf32(v.w);
    *(float4*)(p.dst[s] + i) = v;
}

// ---------------- qt = q + txt ----------------
__global__ void add_txt_k(const float* __restrict__ q, const float* __restrict__ txt) {
    size_t idx = (size_t)blockIdx.x * 256 + threadIdx.x;
    if (idx >= (size_t)B_*L_*D_) return;
    int b = (int)(idx / ((size_t)L_*D_));
    int c = (int)(idx % D_);
    g_qt[idx] = q[idx] + txt[b*D_ + c];
}

// ---------------- pipelined tf32 GEMM, 4 warps, warp tile 64x(16*NF) ----------------
struct GemmP {
    const float* A[3]; const float* Bw[3]; const float* bias[3]; float* C[3];
    const float* resid;
    int N, K, lda, ldb, ldc, nSets, Hp, roundOut;
    long long aSB, aSH, bSB, bSH, cSB, cSH;
    float alpha;
};

template<bool TRANSB, int NF>
__global__ __launch_bounds__(128) void gemm_k(GemmP p)
{
    constexpr int BN   = 32*NF;
    constexpr int ASTR = 36;
    constexpr int BSTR = TRANSB ? 36 : (BN + 4);
    constexpr int ASZ  = 128*ASTR;
    constexpr int BSZ  = TRANSB ? BN*36 : 32*(BN+4);
    extern __shared__ float dsm[];
    float* sA = dsm;
    float* sB = dsm + 2*ASZ;
    float* stag = sB + 2*BSZ;

    int z = blockIdx.z;
    int set = z % p.nSets; int rest = z / p.nSets;
    int zh = rest % p.Hp, zb = rest / p.Hp;
    const float* A  = p.A[set]  + zb*p.aSB + zh*p.aSH;
    const float* Bw = p.Bw[set] + zb*p.bSB + zh*p.bSH;
    const float* bias = p.bias[set];
    float* C = p.C[set] + zb*p.cSB + zh*p.cSH;

    int m0 = blockIdx.x*128, n0 = blockIdx.y*BN;
    int tid = threadIdx.x, lane = tid&31, wid = tid>>5;
    int wm = wid>>1, wn = wid&1;

    auto prefetch = [&](int kt, int buf) {
        float* dA = sA + buf*ASZ; float* dB = sB + buf*BSZ;
        #pragma unroll
        for (int i=0;i<8;i++) {
            int idx = tid + i*128; int r = idx>>3, c = (idx&7)*4;
            cp16(dA + r*ASTR + c, A + (size_t)(m0+r)*p.lda + kt + c);
        }
        if (TRANSB) {
            #pragma unroll
            for (int i=0;i<BN/16;i++) {
                int idx = tid + i*128; int r = idx>>3, c = (idx&7)*4;
                cp16(dB + r*36 + c, Bw + (size_t)(n0+r)*p.ldb + kt + c);
            }
        } else {
            #pragma unroll
            for (int i=0;i<BN/16;i++) {
                int idx = tid + i*128;
                int r = idx/(BN/4), c = (idx%(BN/4))*4;
                cp16(dB + r*BSTR + c, Bw + (size_t)(kt+r)*p.ldb + n0 + c);
            }
        }
        CP_COMMIT();
    };

    wmma::fragment<wmma::accumulator,16,16,8,float> acc[4][NF];
    #pragma unroll
    for (int i=0;i<4;i++)
    #pragma unroll
    for (int j=0;j<NF;j++) wmma::fill_fragment(acc[i][j], 0.f);

    prefetch(0, 0);
    int nk = p.K/32;
    for (int k=0;k<nk;k++) {
        int cur = k&1;
        if (k+1 < nk) {
            prefetch((k+1)*32, cur^1);
            asm volatile("cp.async.wait_group 1;\n");
        } else {
            asm volatile("cp.async.wait_group 0;\n");
        }
        __syncthreads();
        const float* cA = sA + cur*ASZ;
        const float* cB = sB + cur*BSZ;
        #pragma unroll
        for (int kk=0;kk<32;kk+=8) {
            wmma::fragment<wmma::matrix_a,16,16,8,wmma::precision::tf32,wmma::row_major> af[4];
            #pragma unroll
            for (int i=0;i<4;i++)
                wmma::load_matrix_sync(af[i], cA + (wm*64+16*i)*ASTR + kk, ASTR);
            if (TRANSB) {
                wmma::fragment<wmma::matrix_b,16,16,8,wmma::precision::tf32,wmma::col_major> bf[NF];
                #pragma unroll
                for (int j=0;j<NF;j++)
                    wmma::load_matrix_sync(bf[j], cB + (wn*16*NF+16*j)*36 + kk, 36);
                #pragma unroll
                for (int i=0;i<4;i++)
                #pragma unroll
                for (int j=0;j<NF;j++) wmma::mma_sync(acc[i][j], af[i], bf[j], acc[i][j]);
            } else {
                wmma::fragment<wmma::matrix_b,16,16,8,wmma::precision::tf32,wmma::row_major> bf[NF];
                #pragma unroll
                for (int j=0;j<NF;j++)
                    wmma::load_matrix_sync(bf[j], cB + kk*BSTR + wn*NF*16 + 16*j, BSTR);
                #pragma unroll
                for (int i=0;i<4;i++)
                #pragma unroll
                for (int j=0;j<NF;j++) wmma::mma_sync(acc[i][j], af[i], bf[j], acc[i][j]);
            }
        }
        __syncthreads();
    }

    float* st = stag + wid*320;
    #pragma unroll
    for (int i=0;i<4;i++)
    #pragma unroll
    for (int j=0;j<NF;j++) {
        #pragma unroll
        for (int t=0;t<acc[i][j].num_elements;t++) acc[i][j].x[t] *= p.alpha;
        wmma::store_matrix_sync(st, acc[i][j], 20, wmma::mem_row_major);
        __syncwarp();
        int mb = m0 + wm*64 + i*16;
        int nb = n0 + wn*NF*16 + j*16;
        int r = lane>>1, c0 = (lane&1)*8;
        const float* src = st + r*20 + c0;
        float* dst = C + (size_t)(mb+r)*p.ldc + nb + c0;
        float4 v0 = *(const float4*)(src);
        float4 v1 = *(const float4*)(src+4);
        if (bias) {
            float4 b0 = *(const float4*)(bias + nb + c0);
            float4 b1 = *(const float4*)(bias + nb + c0 + 4);
            v0.x+=b0.x; v0.y+=b0.y; v0.z+=b0.z; v0.w+=b0.w;
            v1.x+=b1.x; v1.y+=b1.y; v1.z+=b1.z; v1.w+=b1.w;
        }
        if (p.resid) {
            const float* rp = p.resid + (size_t)(mb+r)*p.ldc + nb + c0;
            float4 r0 = *(const float4*)(rp);
            float4 r1 = *(const float4*)(rp+4);
            v0.x+=r0.x; v0.y+=r0.y; v0.z+=r0.z; v0.w+=r0.w;
            v1.x+=r1.x; v1.y+=r1.y; v1.z+=r1.z; v1.w+=r1.w;
        }
        if (p.roundOut) {
            v0.x=wmma::__float_to_tf32(v0.x); v0.y=wmma::__float_to_tf32(v0.y);
            v0.z=wmma::__float_to_tf32(v0.z); v0.w=wmma::__float_to_tf32(v0.w);
            v1.x=wmma::__float_to_tf32(v1.x); v1.y=wmma::__float_to_tf32(v1.y);
            v1.z=wmma::__float_to_tf32(v1.z); v1.w=wmma::__float_to_tf32(v1.w);
        }
        *(float4*)(dst) = v0;
        *(float4*)(dst+4) = v1;
        __syncwarp();
    }
}

// ---------------- small GEMM for cond (N=72), inline tf32 conversion ----------------
__global__ __launch_bounds__(256) void gemm_s(
    const float* __restrict__ A, const float* __restrict__ Bw,
    const float* __restrict__ bias, float* __restrict__ C, int N, int K)
{
    constexpr int BN = 64;
    __shared__ float sA[128*36];
    __shared__ float sB[32*68];
    __shared__ float stag[8][16*20];
    int m0 = blockIdx.x*128, n0 = blockIdx.y*BN;
    int tid = threadIdx.x, lane = tid&31, wid = tid>>5;
    int wm = wid>>1, wn = wid&1;

    wmma::fragment<wmma::accumulator,16,16,8,float> acc[2][2];
    #pragma unroll
    for (int i=0;i<2;i++)
    #pragma unroll
    for (int j=0;j<2;j++) wmma::fill_fragment(acc[i][j], 0.f);

    for (int kt=0; kt<K; kt+=32) {
        __syncthreads();
        #pragma unroll
        for (int i=0;i<4;i++) {
            int idx = tid + i*256; int r = idx>>3, c = (idx&7)*4;
            float4 v = *(const float4*)(A + (size_t)(m0+r)*K + kt + c);
            v.x = wmma::__float_to_tf32(v.x); v.y = wmma::__float_to_tf32(v.y);
            v.z = wmma::__float_to_tf32(v.z); v.w = wmma::__float_to_tf32(v.w);
            *(float4*)(sA + r*36 + c) = v;
        }
        #pragma unroll
        for (int i=0;i<2;i++) {
            int idx = tid + i*256; int r = idx>>4, c = (idx&15)*4;
            const float* bp = Bw + (size_t)(kt+r)*N + n0 + c;
            float4 v;
            v.x = (n0+c+0<N)? bp[0]:0.f; v.y = (n0+c+1<N)? bp[1]:0.f;
            v.z = (n0+c+2<N)? bp[2]:0.f; v.w = (n0+c+3<N)? bp[3]:0.f;
            v.x = wmma::__float_to_tf32(v.x); v.y = wmma::__float_to_tf32(v.y);
            v.z = wmma::__float_to_tf32(v.z); v.w = wmma::__float_to_tf32(v.w);
            *(float4*)(sB + r*68 + c) = v;
        }
        __syncthreads();
        #pragma unroll
        for (int kk=0;kk<32;kk+=8) {
            wmma::fragment<wmma::matrix_a,16,16,8,wmma::precision::tf32,wmma::row_major> af[2];
            #pragma unroll
            for (int i=0;i<2;i++)
                wmma::load_matrix_sync(af[i], sA + (wm*32+16*i)*36 + kk, 36);
            wmma::fragment<wmma::matrix_b,16,16,8,wmma::precision::tf32,wmma::row_major> bf[2];
            #pragma unroll
            for (int j=0;j<2;j++)
                wmma::load_matrix_sync(bf[j], sB + kk*68 + wn*32 + 16*j, 68);
            #pragma unroll
            for (int i=0;i<2;i++)
            #pragma unroll
            for (int j=0;j<2;j++) wmma::mma_sync(acc[i][j], af[i], bf[j], acc[i][j]);
        }
    }
    #pragma unroll
    for (int i=0;i<2;i++)
    #pragma unroll
    for (int j=0;j<2;j++) {
        wmma::store_matrix_sync(stag[wid], acc[i][j], 20, wmma::mem_row_major);
        __syncwarp();
        int mb = m0 + wm*32 + i*16;
        int nb = n0 + wn*32 + j*16;
        int r = lane>>1, c0 = (lane&1)*8;
        const float* src = stag[wid] + r*20 + c0;
        #pragma unroll
        for (int t=0;t<8;t++) {
            int n = nb + c0 + t;
            if (n < N) C[(size_t)(mb+r)*N + n] = src[t] + bias[n];
        }
        __syncwarp();
    }
}

// ---------------- fused spatial-gate + softmax (in-place on P) ----------------
__global__ __launch_bounds__(256) void fuse_softmax_k(
    const float* __restrict__ ploc, const void* __restrict__ maskp,
    float* __restrict__ P)
{
    int bl = blockIdx.x; int b = bl >> 9;
    __shared__ float splc[512*5];
    __shared__ float ssw[72];
    __shared__ unsigned char smask[512];
    __shared__ float red[8];
    int tid = threadIdx.x;
    const float* pl = ploc + (size_t)bl*512*5;
    for (int i=tid; i<2560; i+=256) splc[i] = pl[i];
    if (tid < 72) ssw[tid] = g_sw[(size_t)bl*72 + tid];
    int mode = g_mask_mode;
    for (int i=tid; i<512; i+=256)
        smask[i] = (unsigned char)is_masked(maskp, b*L_ + i, mode);
    __syncthreads();
    int l = bl & 511;
    for (int h=0; h<H_; h++) {
        float* Srow = P + (((size_t)b*H_ + h)*L_ + l)*L_;
        float b0 = ssw[h*6], w0=ssw[h*6+1], w1=ssw[h*6+2], w2=ssw[h*6+3],
              w3=ssw[h*6+4], w4=ssw[h*6+5];
        float x0, x1;
        {
            int t = tid;
            if (smask[t]) x0 = -INFINITY;
            else {
                const float* pp = splc + t*5;
                float loc = b0 + w0*pp[0]+w1*pp[1]+w2*pp[2]+w3*pp[3]+w4*pp[4];
                float sg = 1.f/(1.f+__expf(-loc));
                x0 = Srow[t] + __logf(fmaxf(sg, 1e-6f));
            }
            t = tid + 256;
            if (smask[t]) x1 = -INFINITY;
            else {
                const float* pp = splc + t*5;
                float loc = b0 + w0*pp[0]+w1*pp[1]+w2*pp[2]+w3*pp[3]+w4*pp[4];
                float sg = 1.f/(1.f+__expf(-loc));
                x1 = Srow[t] + __logf(fmaxf(sg, 1e-6f));
            }
        }
        float mx = fmaxf(x0, x1);
        #pragma unroll
        for (int o=16;o;o>>=1) mx = fmaxf(mx, __shfl_xor_sync(~0u, mx, o));
        if ((tid&31)==0) red[tid>>5] = mx;
        __syncthreads();
        mx = fmaxf(fmaxf(fmaxf(red[0],red[1]),fmaxf(red[2],red[3])),
                   fmaxf(fmaxf(red[4],red[5]),fmaxf(red[6],red[7])));
        float e0 = smask[tid]      ? 0.f : __expf(x0 - mx);
        float e1 = smask[tid+256]  ? 0.f : __expf(x1 - mx);
        float s = e0 + e1;
        #pragma unroll
        for (int o=16;o;o>>=1) s += __shfl_xor_sync(~0u, s, o);
        __syncthreads();
        if ((tid&31)==0) red[tid>>5] = s;
        __syncthreads();
        s = red[0]+red[1]+red[2]+red[3]+red[4]+red[5]+red[6]+red[7];
        float inv = 1.f/s;
        Srow[tid] = e0*inv;
        Srow[tid+256] = e1*inv;
        __syncthreads();
    }
}

// ---------------- LayerNorm ----------------
__global__ __launch_bounds__(256) void ln_k(
    const float* __restrict__ sc, const float* __restrict__ bs, float* __restrict__ Y)
{
    int row = blockIdx.x;
    const float* x = g_x + (size_t)row*D_;
    float* y = Y + (size_t)row*D_;
    __shared__ float r1[8], r2[8];
    int tid = threadIdx.x;
    float v0=x[tid], v1=x[tid+256], v2=x[tid+512];
    float s = v0+v1+v2, q = v0*v0+v1*v1+v2*v2;
    #pragma unroll
    for (int o=16;o;o>>=1) {
        s += __shfl_xor_sync(~0u, s, o);
        q += __shfl_xor_sync(~0u, q, o);
    }
    if ((tid&31)==0) { r1[tid>>5]=s; r2[tid>>5]=q; }
    __syncthreads();
    s = r1[0]+r1[1]+r1[2]+r1[3]+r1[4]+r1[5]+r1[6]+r1[7];
    q = r2[0]+r2[1]+r2[2]+r2[3]+r2[4]+r2[5]+r2[6]+r2[7];
    float mu = s * (1.f/D_);
    float var = q * (1.f/D_) - mu*mu;
    float r = rsqrtf(var + 1e-5f);
    y[tid]     = (v0-mu)*r*sc[tid]     + bs[tid];
    y[tid+256] = (v1-mu)*r*sc[tid+256] + bs[tid+256];
    y[tid+512] = (v2-mu)*r*sc[tid+512] + bs[tid+512];
}

// ---------------- host ----------------
extern "C" void kernel_launch(void* const* d_in, const int* in_sizes, int n_in,
                              void* d_out, int out_size) {
    const float* q    = (const float*)d_in[0];
    const float* k    = (const float*)d_in[1];
    const float* v    = (const float*)d_in[2];
    const float* ploc = (const float*)d_in[3];
    const float* txt  = (const float*)d_in[4];
    const void*  mask = d_in[5];
    const float* Wq = (const float*)d_in[6],  *bq = (const float*)d_in[7];
    const float* Wk = (const float*)d_in[8],  *bk = (const float*)d_in[9];
    const float* Wv = (const float*)d_in[10], *bv = (const float*)d_in[11];
    const float* Wfc= (const float*)d_in[12], *bfc= (const float*)d_in[13];
    const float* Wc = (const float*)d_in[14], *bc = (const float*)d_in[15];
    const float* lns= (const float*)d_in[16], *lnb= (const float*)d_in[17];

    float* y = (float*)d_out;
    float* P = y + (size_t)B_*L_*D_;

    void *p0,*p1,*p2,*p3,*p4,*p5,*p6,*p7,*p8,*p9,*pa,*pb,*pc,*pd;
    cudaGetSymbolAddress(&p0, g_qh);  cudaGetSymbolAddress(&p1, g_kh);
    cudaGetSymbolAddress(&p2, g_vh);  cudaGetSymbolAddress(&p3, g_qt);
    cudaGetSymbolAddress(&p4, g_ctx); cudaGetSymbolAddress(&p5, g_x);
    cudaGetSymbolAddress(&p6, g_sw);  cudaGetSymbolAddress(&p7, g_qc);
    cudaGetSymbolAddress(&p8, g_kc);  cudaGetSymbolAddress(&p9, g_vc);
    cudaGetSymbolAddress(&pa, g_Wqc); cudaGetSymbolAddress(&pb, g_Wkc);
    cudaGetSymbolAddress(&pc, g_Wvc); cudaGetSymbolAddress(&pd, g_Wfcc);
    float *qh=(float*)p0, *kh=(float*)p1, *vh=(float*)p2, *qt=(float*)p3;
    float *ctx=(float*)p4, *xx=(float*)p5, *sw=(float*)p6;
    float *qc=(float*)p7, *kc=(float*)p8, *vc=(float*)p9;
    float *Wqc=(float*)pa, *Wkc=(float*)pb, *Wvc=(float*)pc, *Wfcc=(float*)pd;

    const int M = B_*L_;
    const int NQ = M*D_, NW = D_*D_;

    constexpr int GS_F4 = (2*(128*36) + 2*(32*132) + 4*320) * 4;  // 75776
    constexpr int GS_T4 = (2*(128*36) + 2*(128*36) + 4*320) * 4;  // 79616
    constexpr int GS_F2 = (2*(128*36) + 2*(32*68)  + 4*320) * 4;  // 59392
    cudaFuncSetAttribute(gemm_k<false,4>, cudaFuncAttributeMaxDynamicSharedMemorySize, GS_F4);
    cudaFuncSetAttribute(gemm_k<true,4>,  cudaFuncAttributeMaxDynamicSharedMemorySize, GS_T4);
    cudaFuncSetAttribute(gemm_k<false,2>, cudaFuncAttributeMaxDynamicSharedMemorySize, GS_F2);

    detect_mask_k<<<1,256>>>((const unsigned int*)mask);

    { // RN pre-rounding: q,k,v + Wq,Wk,Wv,Wfc
        ConvP cp{};
        cp.src[0]=q;   cp.dst[0]=qc;   cp.n[0]=NQ;
        cp.src[1]=k;   cp.dst[1]=kc;   cp.n[1]=NQ;
        cp.src[2]=v;   cp.dst[2]=vc;   cp.n[2]=NQ;
        cp.src[3]=Wq;  cp.dst[3]=Wqc;  cp.n[3]=NW;
        cp.src[4]=Wk;  cp.dst[4]=Wkc;  cp.n[4]=NW;
        cp.src[5]=Wv;  cp.dst[5]=Wvc;  cp.n[5]=NW;
        cp.src[6]=Wfc; cp.dst[6]=Wfcc; cp.n[6]=NW;
        conv_k<<<dim3(NQ/1024, 7), 256>>>(cp);
    }
    add_txt_k<<<(NQ + 255)/256, 256>>>(q, txt);

    { // Q/K/V projections, one launch, rounded outputs
        GemmP g{};
        g.A[0]=qc; g.A[1]=kc; g.A[2]=vc;
        g.Bw[0]=Wqc; g.Bw[1]=Wkc; g.Bw[2]=Wvc;
        g.bias[0]=bq; g.bias[1]=bk; g.bias[2]=bv;
        g.C[0]=qh; g.C[1]=kh; g.C[2]=vh;
        g.N=D_; g.K=D_; g.lda=D_; g.ldb=D_; g.ldc=D_;
        g.nSets=3; g.Hp=1; g.roundOut=1; g.alpha=1.f;
        gemm_k<false,4><<<dim3(M/128, D_/128, 3), 128, GS_F4>>>(g);
    }
    { // cond: (B*L,768) @ (768,72), exact output
        gemm_s<<<dim3(M/128, 2, 1), 256>>>(qt, Wc, bc, sw, 72, D_);
    }
    { // S = 0.125 * Q @ K^T per (b,h) -> P (exact fp32 logits)
        GemmP g{};
        g.A[0]=qh; g.Bw[0]=kh; g.C[0]=P;
        g.N=L_; g.K=64; g.lda=D_; g.ldb=D_; g.ldc=L_;
        g.aSB=(long long)L_*D_; g.aSH=64;
        g.bSB=(long long)L_*D_; g.bSH=64;
        g.cSB=(long long)H_*L_*L_; g.cSH=(long long)L_*L_;
        g.nSets=1; g.Hp=H_; g.roundOut=0; g.alpha=0.125f;
        gemm_k<true,4><<<dim3(L_/128, L_/128, B_*H_), 128, GS_T4>>>(g);
    }
    fuse_softmax_k<<<M, 256>>>(ploc, mask, P);
    { // ctx = P @ V per (b,h); P fed raw (HW tf32 truncation), ctx rounded
        GemmP g{};
        g.A[0]=P; g.Bw[0]=vh; g.C[0]=ctx;
        g.N=64; g.K=L_; g.lda=L_; g.ldb=D_; g.ldc=D_;
        g.aSB=(long long)H_*L_*L_; g.aSH=(long long)L_*L_;
        g.bSB=(long long)L_*D_; g.bSH=64;
        g.cSB=(long long)L_*D_; g.cSH=64;
        g.nSets=1; g.Hp=H_; g.roundOut=1; g.alpha=1.f;
        gemm_k<false,2><<<dim3(L_/128, 1, B_*H_), 128, GS_F2>>>(g);
    }
    { // x = ctx @ Wfc + bfc + q
        GemmP g{};
        g.A[0]=ctx; g.Bw[0]=Wfcc; g.bias[0]=bfc; g.C[0]=xx;
        g.resid=q; g.N=D_; g.K=D_; g.lda=D_; g.ldb=D_; g.ldc=D_;
        g.nSets=1; g.Hp=1; g.roundOut=0; g.alpha=1.f;
        gemm_k<false,4><<<dim3(M/128, D_/128, 1), 128, GS_F4>>>(g);
    }
    ln_k<<<M, 256>>>(lns, lnb, y);
}

// round 9
// speedup vs baseline: 1.7613x; 1.0586x over previous
#include <cuda_runtime.h>
#include <mma.h>
#include <cstdint>
#include <cstddef>

using namespace nvcuda;

#define B_ 32
#define L_ 512
#define D_ 768
#define H_ 12

// ---------------- scratch ----------------
__device__ float g_qh[(size_t)B_*L_*D_];
__device__ float g_kh[(size_t)B_*L_*D_];
__device__ float g_vh[(size_t)B_*L_*D_];
__device__ float g_qt[(size_t)B_*L_*D_];
__device__ float g_ctx[(size_t)B_*L_*D_];
__device__ float g_x[(size_t)B_*L_*D_];
__device__ float g_sw[(size_t)B_*L_*72];
__device__ float g_qc[(size_t)B_*L_*D_];
__device__ float g_kc[(size_t)B_*L_*D_];
__device__ float g_vc[(size_t)B_*L_*D_];
__device__ float g_Wqc[D_*D_];
__device__ float g_Wkc[D_*D_];
__device__ float g_Wvc[D_*D_];
__device__ float g_Wfcc[D_*D_];
__device__ int   g_mask_mode;

// ---------------- cp.async ----------------
__device__ __forceinline__ void cp16(void* s, const void* g) {
    unsigned a = (unsigned)__cvta_generic_to_shared(s);
    asm volatile("cp.async.cg.shared.global [%0], [%1], 16;\n" :: "r"(a), "l"(g));
}
#define CP_COMMIT() asm volatile("cp.async.commit_group;\n")

// ---------------- mask dtype detection ----------------
__global__ void detect_mask_k(const unsigned int* __restrict__ w) {
    __shared__ int sF, sO;
    if (threadIdx.x == 0) { sF = 0; sO = 0; }
    __syncthreads();
    int f = 0, o = 0;
    for (int i = threadIdx.x; i < 4096; i += 256) {
        unsigned v = w[i];
        if (v == 0x3F800000u) f = 1;
        else if (v > 1u) o = 1;
    }
    if (f) atomicOr(&sF, 1);
    if (o) atomicOr(&sO, 1);
    __syncthreads();
    if (threadIdx.x == 0) g_mask_mode = sF ? 1 : (sO ? 2 : 0);
}

__device__ __forceinline__ int is_masked(const void* mp, int idx, int mode) {
    if (mode == 2) return ((const unsigned char*)mp)[idx] != 0;
    if (mode == 1) return ((const float*)mp)[idx] != 0.0f;
    return ((const int*)mp)[idx] != 0;
}

// ---------------- tf32 RN pre-rounding ----------------
struct ConvP { const float* src[7]; float* dst[7]; int n[7]; };
__global__ void conv_k(ConvP p) {
    int s = blockIdx.y;
    int i = (blockIdx.x * 256 + threadIdx.x) * 4;
    if (i >= p.n[s]) return;
    float4 v = *(const float4*)(p.src[s] + i);
    v.x = wmma::__float_to_tf32(v.x); v.y = wmma::__float_to_tf32(v.y);
    v.z = wmma::__float_to_tf32(v.z); v.w = wmma::__float_to_tf32(v.w);
    *(float4*)(p.dst[s] + i) = v;
}

// ---------------- qt = q + txt ----------------
__global__ void add_txt_k(const float* __restrict__ q, const float* __restrict__ txt) {
    size_t idx = (size_t)blockIdx.x * 256 + threadIdx.x;
    if (idx >= (size_t)B_*L_*D_) return;
    int b = (int)(idx / ((size_t)L_*D_));
    int c = (int)(idx % D_);
    g_qt[idx] = q[idx] + txt[b*D_ + c];
}

// ---------------- pipelined tf32 GEMM, 4 warps, warp tile 64x(16*NF) ----------------
struct GemmP {
    const float* A[3]; const float* Bw[3]; const float* bias[3]; float* C[3];
    const float* resid;
    int N, K, lda, ldb, ldc, nSets, Hp, roundOut;
    long long aSB, aSH, bSB, bSH, cSB, cSH;
    float alpha;
};

template<bool TRANSB, int NF, int MINB>
__global__ __launch_bounds__(128, MINB) void gemm_k(GemmP p)
{
    constexpr int BN   = 32*NF;            // block N = 2 warps * 16*NF
    constexpr int ASTR = 36;
    constexpr int BSTR = TRANSB ? 36 : (BN + 4);
    constexpr int ASZ  = 128*ASTR;
    constexpr int BSZ  = TRANSB ? BN*36 : 32*(BN+4);
    extern __shared__ float dsm[];
    float* sA = dsm;
    float* sB = dsm + 2*ASZ;
    float* stag = sB + 2*BSZ;

    int z = blockIdx.z;
    int set = z % p.nSets; int rest = z / p.nSets;
    int zh = rest % p.Hp, zb = rest / p.Hp;
    const float* A  = p.A[set]  + zb*p.aSB + zh*p.aSH;
    const float* Bw = p.Bw[set] + zb*p.bSB + zh*p.bSH;
    const float* bias = p.bias[set];
    float* C = p.C[set] + zb*p.cSB + zh*p.cSH;

    int m0 = blockIdx.x*128, n0 = blockIdx.y*BN;
    int tid = threadIdx.x, lane = tid&31, wid = tid>>5;
    int wm = wid>>1, wn = wid&1;

    auto prefetch = [&](int kt, int buf) {
        float* dA = sA + buf*ASZ; float* dB = sB + buf*BSZ;
        #pragma unroll
        for (int i=0;i<8;i++) {
            int idx = tid + i*128; int r = idx>>3, c = (idx&7)*4;
            cp16(dA + r*ASTR + c, A + (size_t)(m0+r)*p.lda + kt + c);
        }
        if (TRANSB) {
            #pragma unroll
            for (int i=0;i<BN/16;i++) {
                int idx = tid + i*128; int r = idx>>3, c = (idx&7)*4;
                cp16(dB + r*36 + c, Bw + (size_t)(n0+r)*p.ldb + kt + c);
            }
        } else {
            #pragma unroll
            for (int i=0;i<BN/16;i++) {
                int idx = tid + i*128;
                int r = idx/(BN/4), c = (idx%(BN/4))*4;
                cp16(dB + r*BSTR + c, Bw + (size_t)(kt+r)*p.ldb + n0 + c);
            }
        }
        CP_COMMIT();
    };

    wmma::fragment<wmma::accumulator,16,16,8,float> acc[4][NF];
    #pragma unroll
    for (int i=0;i<4;i++)
    #pragma unroll
    for (int j=0;j<NF;j++) wmma::fill_fragment(acc[i][j], 0.f);

    prefetch(0, 0);
    int nk = p.K/32;
    for (int k=0;k<nk;k++) {
        int cur = k&1;
        if (k+1 < nk) {
            prefetch((k+1)*32, cur^1);
            asm volatile("cp.async.wait_group 1;\n");
        } else {
            asm volatile("cp.async.wait_group 0;\n");
        }
        __syncthreads();
        const float* cA = sA + cur*ASZ;
        const float* cB = sB + cur*BSZ;
        #pragma unroll
        for (int kk=0;kk<32;kk+=8) {
            wmma::fragment<wmma::matrix_a,16,16,8,wmma::precision::tf32,wmma::row_major> af[4];
            #pragma unroll
            for (int i=0;i<4;i++)
                wmma::load_matrix_sync(af[i], cA + (wm*64+16*i)*ASTR + kk, ASTR);
            if (TRANSB) {
                wmma::fragment<wmma::matrix_b,16,16,8,wmma::precision::tf32,wmma::col_major> bf[NF];
                #pragma unroll
                for (int j=0;j<NF;j++)
                    wmma::load_matrix_sync(bf[j], cB + (wn*16*NF+16*j)*36 + kk, 36);
                #pragma unroll
                for (int i=0;i<4;i++)
                #pragma unroll
                for (int j=0;j<NF;j++) wmma::mma_sync(acc[i][j], af[i], bf[j], acc[i][j]);
            } else {
                wmma::fragment<wmma::matrix_b,16,16,8,wmma::precision::tf32,wmma::row_major> bf[NF];
                #pragma unroll
                for (int j=0;j<NF;j++)
                    wmma::load_matrix_sync(bf[j], cB + kk*BSTR + wn*NF*16 + 16*j, BSTR);
                #pragma unroll
                for (int i=0;i<4;i++)
                #pragma unroll
                for (int j=0;j<NF;j++) wmma::mma_sync(acc[i][j], af[i], bf[j], acc[i][j]);
            }
        }
        __syncthreads();
    }

    float* st = stag + wid*320;
    #pragma unroll
    for (int i=0;i<4;i++)
    #pragma unroll
    for (int j=0;j<NF;j++) {
        #pragma unroll
        for (int t=0;t<acc[i][j].num_elements;t++) acc[i][j].x[t] *= p.alpha;
        wmma::store_matrix_sync(st, acc[i][j], 20, wmma::mem_row_major);
        __syncwarp();
        int mb = m0 + wm*64 + i*16;
        int nb = n0 + wn*NF*16 + j*16;
        int r = lane>>1, c0 = (lane&1)*8;
        const float* src = st + r*20 + c0;
        float* dst = C + (size_t)(mb+r)*p.ldc + nb + c0;
        float4 v0 = *(const float4*)(src);
        float4 v1 = *(const float4*)(src+4);
        if (bias) {
            float4 b0 = *(const float4*)(bias + nb + c0);
            float4 b1 = *(const float4*)(bias + nb + c0 + 4);
            v0.x+=b0.x; v0.y+=b0.y; v0.z+=b0.z; v0.w+=b0.w;
            v1.x+=b1.x; v1.y+=b1.y; v1.z+=b1.z; v1.w+=b1.w;
        }
        if (p.resid) {
            const float* rp = p.resid + (size_t)(mb+r)*p.ldc + nb + c0;
            float4 r0 = *(const float4*)(rp);
            float4 r1 = *(const float4*)(rp+4);
            v0.x+=r0.x; v0.y+=r0.y; v0.z+=r0.z; v0.w+=r0.w;
            v1.x+=r1.x; v1.y+=r1.y; v1.z+=r1.z; v1.w+=r1.w;
        }
        if (p.roundOut) {
            v0.x=wmma::__float_to_tf32(v0.x); v0.y=wmma::__float_to_tf32(v0.y);
            v0.z=wmma::__float_to_tf32(v0.z); v0.w=wmma::__float_to_tf32(v0.w);
            v1.x=wmma::__float_to_tf32(v1.x); v1.y=wmma::__float_to_tf32(v1.y);
            v1.z=wmma::__float_to_tf32(v1.z); v1.w=wmma::__float_to_tf32(v1.w);
        }
        *(float4*)(dst) = v0;
        *(float4*)(dst+4) = v1;
        __syncwarp();
    }
}

// ---------------- small GEMM for cond (N=72) ----------------
__global__ __launch_bounds__(256) void gemm_s(
    const float* __restrict__ A, const float* __restrict__ Bw,
    const float* __restrict__ bias, float* __restrict__ C, int N, int K)
{
    constexpr int BN = 64;
    __shared__ float sA[128*36];
    __shared__ float sB[32*68];
    __shared__ float stag[8][16*20];
    int m0 = blockIdx.x*128, n0 = blockIdx.y*BN;
    int tid = threadIdx.x, lane = tid&31, wid = tid>>5;
    int wm = wid>>1, wn = wid&1;

    wmma::fragment<wmma::accumulator,16,16,8,float> acc[2][2];
    #pragma unroll
    for (int i=0;i<2;i++)
    #pragma unroll
    for (int j=0;j<2;j++) wmma::fill_fragment(acc[i][j], 0.f);

    for (int kt=0; kt<K; kt+=32) {
        __syncthreads();
        #pragma unroll
        for (int i=0;i<4;i++) {
            int idx = tid + i*256; int r = idx>>3, c = (idx&7)*4;
            float4 v = *(const float4*)(A + (size_t)(m0+r)*K + kt + c);
            v.x = wmma::__float_to_tf32(v.x); v.y = wmma::__float_to_tf32(v.y);
            v.z = wmma::__float_to_tf32(v.z); v.w = wmma::__float_to_tf32(v.w);
            *(float4*)(sA + r*36 + c) = v;
        }
        #pragma unroll
        for (int i=0;i<2;i++) {
            int idx = tid + i*256; int r = idx>>4, c = (idx&15)*4;
            const float* bp = Bw + (size_t)(kt+r)*N + n0 + c;
            float4 v;
            v.x = (n0+c+0<N)? bp[0]:0.f; v.y = (n0+c+1<N)? bp[1]:0.f;
            v.z = (n0+c+2<N)? bp[2]:0.f; v.w = (n0+c+3<N)? bp[3]:0.f;
            v.x = wmma::__float_to_tf32(v.x); v.y = wmma::__float_to_tf32(v.y);
            v.z = wmma::__float_to_tf32(v.z); v.w = wmma::__float_to_tf32(v.w);
            *(float4*)(sB + r*68 + c) = v;
        }
        __syncthreads();
        #pragma unroll
        for (int kk=0;kk<32;kk+=8) {
            wmma::fragment<wmma::matrix_a,16,16,8,wmma::precision::tf32,wmma::row_major> af[2];
            #pragma unroll
            for (int i=0;i<2;i++)
                wmma::load_matrix_sync(af[i], sA + (wm*32+16*i)*36 + kk, 36);
            wmma::fragment<wmma::matrix_b,16,16,8,wmma::precision::tf32,wmma::row_major> bf[2];
            #pragma unroll
            for (int j=0;j<2;j++)
                wmma::load_matrix_sync(bf[j], sB + kk*68 + wn*32 + 16*j, 68);
            #pragma unroll
            for (int i=0;i<2;i++)
            #pragma unroll
            for (int j=0;j<2;j++) wmma::mma_sync(acc[i][j], af[i], bf[j], acc[i][j]);
        }
    }
    #pragma unroll
    for (int i=0;i<2;i++)
    #pragma unroll
    for (int j=0;j<2;j++) {
        wmma::store_matrix_sync(stag[wid], acc[i][j], 20, wmma::mem_row_major);
        __syncwarp();
        int mb = m0 + wm*32 + i*16;
        int nb = n0 + wn*32 + j*16;
        int r = lane>>1, c0 = (lane&1)*8;
        const float* src = stag[wid] + r*20 + c0;
        #pragma unroll
        for (int t=0;t<8;t++) {
            int n = nb + c0 + t;
            if (n < N) C[(size_t)(mb+r)*N + n] = src[t] + bias[n];
        }
        __syncwarp();
    }
}

// ---------------- fused spatial-gate + softmax: warp-per-head ----------------
__global__ __launch_bounds__(384) void fuse_softmax_k(
    const float* __restrict__ ploc, const void* __restrict__ maskp,
    float* __restrict__ P)
{
    int bl = blockIdx.x; int b = bl >> 9; int l = bl & 511;
    __shared__ float splcT[5*512];            // transposed: [dim][t]
    __shared__ unsigned char smask[512];
    int tid = threadIdx.x, lane = tid&31, h = tid>>5;   // 12 warps = 12 heads

    const float* pl = ploc + (size_t)bl*2560;
    for (int i=tid; i<2560; i+=384) {
        int t = i/5, d = i%5;                  // global read coalesced
        splcT[d*512 + t] = pl[i];
    }
    int mode = g_mask_mode;
    for (int i=tid; i<512; i+=384)
        smask[i] = (unsigned char)is_masked(maskp, b*L_ + i, mode);
    __syncthreads();

    const float* swp = g_sw + (size_t)bl*72 + h*6;
    float c0=swp[0], c1=swp[1], c2=swp[2], c3=swp[3], c4=swp[4], c5=swp[5];
    float* Srow = P + (((size_t)b*H_ + h)*L_ + l)*L_;

    float4 xv[4];
    float mx = -INFINITY;
    #pragma unroll
    for (int j=0;j<4;j++) {
        int t = j*128 + lane*4;
        float4 sv = *(const float4*)(Srow + t);
        float4 p0 = *(const float4*)(splcT + 0*512 + t);
        float4 p1 = *(const float4*)(splcT + 1*512 + t);
        float4 p2 = *(const float4*)(splcT + 2*512 + t);
        float4 p3 = *(const float4*)(splcT + 3*512 + t);
        float4 p4 = *(const float4*)(splcT + 4*512 + t);
        uchar4 mk = *(const uchar4*)(smask + t);
        float4 r;
        {
            float loc = c0 + c1*p0.x + c2*p1.x + c3*p2.x + c4*p3.x + c5*p4.x;
            float sg = 1.f/(1.f+__expf(-loc));
            r.x = mk.x ? -INFINITY : sv.x + __logf(fmaxf(sg,1e-6f));
        }
        {
            float loc = c0 + c1*p0.y + c2*p1.y + c3*p2.y + c4*p3.y + c5*p4.y;
            float sg = 1.f/(1.f+__expf(-loc));
            r.y = mk.y ? -INFINITY : sv.y + __logf(fmaxf(sg,1e-6f));
        }
        {
            float loc = c0 + c1*p0.z + c2*p1.z + c3*p2.z + c4*p3.z + c5*p4.z;
            float sg = 1.f/(1.f+__expf(-loc));
            r.z = mk.z ? -INFINITY : sv.z + __logf(fmaxf(sg,1e-6f));
        }
        {
            float loc = c0 + c1*p0.w + c2*p1.w + c3*p2.w + c4*p3.w + c5*p4.w;
            float sg = 1.f/(1.f+__expf(-loc));
            r.w = mk.w ? -INFINITY : sv.w + __logf(fmaxf(sg,1e-6f));
        }
        xv[j] = r;
        mx = fmaxf(mx, fmaxf(fmaxf(r.x,r.y), fmaxf(r.z,r.w)));
    }
    #pragma unroll
    for (int o=16;o;o>>=1) mx = fmaxf(mx, __shfl_xor_sync(~0u, mx, o));
    float s = 0.f;
    #pragma unroll
    for (int j=0;j<4;j++) {
        float4 r = xv[j];
        r.x = (r.x == -INFINITY) ? 0.f : __expf(r.x - mx);
        r.y = (r.y == -INFINITY) ? 0.f : __expf(r.y - mx);
        r.z = (r.z == -INFINITY) ? 0.f : __expf(r.z - mx);
        r.w = (r.w == -INFINITY) ? 0.f : __expf(r.w - mx);
        xv[j] = r;
        s += r.x + r.y + r.z + r.w;
    }
    #pragma unroll
    for (int o=16;o;o>>=1) s += __shfl_xor_sync(~0u, s, o);
    float inv = 1.f/s;
    #pragma unroll
    for (int j=0;j<4;j++) {
        int t = j*128 + lane*4;
        float4 r = xv[j];
        r.x *= inv; r.y *= inv; r.z *= inv; r.w *= inv;
        *(float4*)(Srow + t) = r;
    }
}

// ---------------- LayerNorm ----------------
__global__ __launch_bounds__(256) void ln_k(
    const float* __restrict__ sc, const float* __restrict__ bs, float* __restrict__ Y)
{
    int row = blockIdx.x;
    const float* x = g_x + (size_t)row*D_;
    float* y = Y + (size_t)row*D_;
    __shared__ float r1[8], r2[8];
    int tid = threadIdx.x;
    float v0=x[tid], v1=x[tid+256], v2=x[tid+512];
    float s = v0+v1+v2, q = v0*v0+v1*v1+v2*v2;
    #pragma unroll
    for (int o=16;o;o>>=1) {
        s += __shfl_xor_sync(~0u, s, o);
        q += __shfl_xor_sync(~0u, q, o);
    }
    if ((tid&31)==0) { r1[tid>>5]=s; r2[tid>>5]=q; }
    __syncthreads();
    s = r1[0]+r1[1]+r1[2]+r1[3]+r1[4]+r1[5]+r1[6]+r1[7];
    q = r2[0]+r2[1]+r2[2]+r2[3]+r2[4]+r2[5]+r2[6]+r2[7];
    float mu = s * (1.f/D_);
    float var = q * (1.f/D_) - mu*mu;
    float r = rsqrtf(var + 1e-5f);
    y[tid]     = (v0-mu)*r*sc[tid]     + bs[tid];
    y[tid+256] = (v1-mu)*r*sc[tid+256] + bs[tid+256];
    y[tid+512] = (v2-mu)*r*sc[tid+512] + bs[tid+512];
}

// ---------------- host ----------------
extern "C" void kernel_launch(void* const* d_in, const int* in_sizes, int n_in,
                              void* d_out, int out_size) {
    const float* q    = (const float*)d_in[0];
    const float* k    = (const float*)d_in[1];
    const float* v    = (const float*)d_in[2];
    const float* ploc = (const float*)d_in[3];
    const float* txt  = (const float*)d_in[4];
    const void*  mask = d_in[5];
    const float* Wq = (const float*)d_in[6],  *bq = (const float*)d_in[7];
    const float* Wk = (const float*)d_in[8],  *bk = (const float*)d_in[9];
    const float* Wv = (const float*)d_in[10], *bv = (const float*)d_in[11];
    const float* Wfc= (const float*)d_in[12], *bfc= (const float*)d_in[13];
    const float* Wc = (const float*)d_in[14], *bc = (const float*)d_in[15];
    const float* lns= (const float*)d_in[16], *lnb= (const float*)d_in[17];

    float* y = (float*)d_out;
    float* P = y + (size_t)B_*L_*D_;

    void *p0,*p1,*p2,*p3,*p4,*p5,*p6,*p7,*p8,*p9,*pa,*pb,*pc,*pd;
    cudaGetSymbolAddress(&p0, g_qh);  cudaGetSymbolAddress(&p1, g_kh);
    cudaGetSymbolAddress(&p2, g_vh);  cudaGetSymbolAddress(&p3, g_qt);
    cudaGetSymbolAddress(&p4, g_ctx); cudaGetSymbolAddress(&p5, g_x);
    cudaGetSymbolAddress(&p6, g_sw);  cudaGetSymbolAddress(&p7, g_qc);
    cudaGetSymbolAddress(&p8, g_kc);  cudaGetSymbolAddress(&p9, g_vc);
    cudaGetSymbolAddress(&pa, g_Wqc); cudaGetSymbolAddress(&pb, g_Wkc);
    cudaGetSymbolAddress(&pc, g_Wvc); cudaGetSymbolAddress(&pd, g_Wfcc);
    float *qh=(float*)p0, *kh=(float*)p1, *vh=(float*)p2, *qt=(float*)p3;
    float *ctx=(float*)p4, *xx=(float*)p5, *sw=(float*)p6;
    float *qc=(float*)p7, *kc=(float*)p8, *vc=(float*)p9;
    float *Wqc=(float*)pa, *Wkc=(float*)pb, *Wvc=(float*)pc, *Wfcc=(float*)pd;

    const int M = B_*L_;
    const int NQ = M*D_, NW = D_*D_;

    constexpr int GS_F3 = (2*(128*36) + 2*(32*100) + 4*320) * 4;  // 67584
    constexpr int GS_T4 = (2*(128*36) + 2*(128*36) + 4*320) * 4;  // 78848
    constexpr int GS_F2 = (2*(128*36) + 2*(32*68)  + 4*320) * 4;  // 59392
    cudaFuncSetAttribute(gemm_k<false,3,3>, cudaFuncAttributeMaxDynamicSharedMemorySize, GS_F3);
    cudaFuncSetAttribute(gemm_k<true,4,1>,  cudaFuncAttributeMaxDynamicSharedMemorySize, GS_T4);
    cudaFuncSetAttribute(gemm_k<false,2,3>, cudaFuncAttributeMaxDynamicSharedMemorySize, GS_F2);

    detect_mask_k<<<1,256>>>((const unsigned int*)mask);

    { // RN pre-rounding: q,k,v + Wq,Wk,Wv,Wfc
        ConvP cp{};
        cp.src[0]=q;   cp.dst[0]=qc;   cp.n[0]=NQ;
        cp.src[1]=k;   cp.dst[1]=kc;   cp.n[1]=NQ;
        cp.src[2]=v;   cp.dst[2]=vc;   cp.n[2]=NQ;
        cp.src[3]=Wq;  cp.dst[3]=Wqc;  cp.n[3]=NW;
        cp.src[4]=Wk;  cp.dst[4]=Wkc;  cp.n[4]=NW;
        cp.src[5]=Wv;  cp.dst[5]=Wvc;  cp.n[5]=NW;
        cp.src[6]=Wfc; cp.dst[6]=Wfcc; cp.n[6]=NW;
        conv_k<<<dim3(NQ/1024, 7), 256>>>(cp);
    }
    add_txt_k<<<(NQ + 255)/256, 256>>>(q, txt);

    { // Q/K/V projections, one launch, rounded outputs (BN=96)
        GemmP g{};
        g.A[0]=qc; g.A[1]=kc; g.A[2]=vc;
        g.Bw[0]=Wqc; g.Bw[1]=Wkc; g.Bw[2]=Wvc;
        g.bias[0]=bq; g.bias[1]=bk; g.bias[2]=bv;
        g.C[0]=qh; g.C[1]=kh; g.C[2]=vh;
        g.N=D_; g.K=D_; g.lda=D_; g.ldb=D_; g.ldc=D_;
        g.nSets=3; g.Hp=1; g.roundOut=1; g.alpha=1.f;
        gemm_k<false,3,3><<<dim3(M/128, D_/96, 3), 128, GS_F3>>>(g);
    }
    { // cond
        gemm_s<<<dim3(M/128, 2, 1), 256>>>(qt, Wc, bc, sw, 72, D_);
    }
    { // S = 0.125 * Q @ K^T per (b,h) -> P (exact fp32 logits)
        GemmP g{};
        g.A[0]=qh; g.Bw[0]=kh; g.C[0]=P;
        g.N=L_; g.K=64; g.lda=D_; g.ldb=D_; g.ldc=L_;
        g.aSB=(long long)L_*D_; g.aSH=64;
        g.bSB=(long long)L_*D_; g.bSH=64;
        g.cSB=(long long)H_*L_*L_; g.cSH=(long long)L_*L_;
        g.nSets=1; g.Hp=H_; g.roundOut=0; g.alpha=0.125f;
        gemm_k<true,4,1><<<dim3(L_/128, L_/128, B_*H_), 128, GS_T4>>>(g);
    }
    fuse_softmax_k<<<M, 384>>>(ploc, mask, P);
    { // ctx = P @ V per (b,h)
        GemmP g{};
        g.A[0]=P; g.Bw[0]=vh; g.C[0]=ctx;
        g.N=64; g.K=L_; g.lda=L_; g.ldb=D_; g.ldc=D_;
        g.aSB=(long long)H_*L_*L_; g.aSH=(long long)L_*L_;
        g.bSB=(long long)L_*D_; g.bSH=64;
        g.cSB=(long long)L_*D_; g.cSH=64;
        g.nSets=1; g.Hp=H_; g.roundOut=1; g.alpha=1.f;
        gemm_k<false,2,3><<<dim3(L_/128, 1, B_*H_), 128, GS_F2>>>(g);
    }
    { // x = ctx @ Wfc + bfc + q
        GemmP g{};
        g.A[0]=ctx; g.Bw[0]=Wfcc; g.bias[0]=bfc; g.C[0]=xx;
        g.resid=q; g.N=D_; g.K=D_; g.lda=D_; g.ldb=D_; g.ldc=D_;
        g.nSets=1; g.Hp=1; g.roundOut=0; g.alpha=1.f;
        gemm_k<false,3,3><<<dim3(M/128, D_/96, 1), 128, GS_F3>>>(g);
    }
    ln_k<<<M, 256>>>(lns, lnb, y);
}

// round 11
// speedup vs baseline: 3.1518x; 1.7894x over previous
#include <cuda_runtime.h>
#include <cuda_fp16.h>
#include <mma.h>
#include <cstdint>
#include <cstddef>

using namespace nvcuda;

#define B_ 32
#define L_ 512
#define D_ 768
#define H_ 12

// ---------------- scratch ----------------
__device__ __half g_qch[(size_t)B_*L_*D_];
__device__ __half g_kch[(size_t)B_*L_*D_];
__device__ __half g_vch[(size_t)B_*L_*D_];
__device__ __half g_Wqh[D_*D_];
__device__ __half g_Wkh[D_*D_];
__device__ __half g_Wvh[D_*D_];
__device__ __half g_Wfch[D_*D_];
__device__ __half g_qhh[(size_t)B_*L_*D_];
__device__ __half g_khh[(size_t)B_*L_*D_];
__device__ __half g_vhh[(size_t)B_*L_*D_];
__device__ __half g_ctxh[(size_t)B_*L_*D_];
__device__ __half g_Ph[(size_t)B_*H_*L_*L_];
__device__ float  g_qt[(size_t)B_*L_*D_];
__device__ float  g_x[(size_t)B_*L_*D_];
__device__ float  g_sw[(size_t)B_*L_*72];
__device__ int    g_mask_mode;

// ---------------- cp.async ----------------
__device__ __forceinline__ void cp16(void* s, const void* g) {
    unsigned a = (unsigned)__cvta_generic_to_shared(s);
    asm volatile("cp.async.cg.shared.global [%0], [%1], 16;\n" :: "r"(a), "l"(g));
}
#define CP_COMMIT() asm volatile("cp.async.commit_group;\n")

// ---------------- mask dtype detection ----------------
__global__ void detect_mask_k(const unsigned int* __restrict__ w) {
    __shared__ int sF, sO;
    if (threadIdx.x == 0) { sF = 0; sO = 0; }
    __syncthreads();
    int f = 0, o = 0;
    for (int i = threadIdx.x; i < 4096; i += 256) {
        unsigned v = w[i];
        if (v == 0x3F800000u) f = 1;
        else if (v > 1u) o = 1;
    }
    if (f) atomicOr(&sF, 1);
    if (o) atomicOr(&sO, 1);
    __syncthreads();
    if (threadIdx.x == 0) g_mask_mode = sF ? 1 : (sO ? 2 : 0);
}

__device__ __forceinline__ int is_masked(const void* mp, int idx, int mode) {
    if (mode == 2) return ((const unsigned char*)mp)[idx] != 0;
    if (mode == 1) return ((const float*)mp)[idx] != 0.0f;
    return ((const int*)mp)[idx] != 0;
}

// ---------------- float -> half conversion ----------------
struct ConvP { const float* src[7]; __half* dst[7]; int n[7]; };
__global__ void conv_k(ConvP p) {
    int s = blockIdx.y;
    int i = (blockIdx.x * 256 + threadIdx.x) * 4;
    if (i >= p.n[s]) return;
    float4 v = *(const float4*)(p.src[s] + i);
    __half2 h01 = __floats2half2_rn(v.x, v.y);
    __half2 h23 = __floats2half2_rn(v.z, v.w);
    *(__half2*)(p.dst[s] + i)     = h01;
    *(__half2*)(p.dst[s] + i + 2) = h23;
}

// ---------------- qt = q + txt ----------------
__global__ void add_txt_k(const float* __restrict__ q, const float* __restrict__ txt) {
    size_t idx = (size_t)blockIdx.x * 256 + threadIdx.x;
    if (idx >= (size_t)B_*L_*D_) return;
    int b = (int)(idx / ((size_t)L_*D_));
    int c = (int)(idx % D_);
    g_qt[idx] = q[idx] + txt[b*D_ + c];
}

// ---------------- fp16 pipelined GEMM: BM128 x BN64 x BK32, 4 warps 2x2 ----------------
struct GemmHP {
    const __half* A[3]; const __half* Bw[3]; const float* bias[3];
    void* C[3];
    const float* resid;
    int N, K, lda, ldb, ldc, nSets, Hp;
    long long aSB, aSH, bSB, bSH, cSB, cSH;
    float alpha;
};

#define ASTR 40
#define ASZ  (128*ASTR)          // halfs
#define STAG_OFF 30720           // bytes

template<bool TRANSB, bool OUTH>
__global__ __launch_bounds__(128, 3) void gemm_h(GemmHP p)
{
    constexpr int BSZ  = TRANSB ? 64*40 : 32*72;   // halfs
    extern __shared__ char smraw[];
    __half* sA = (__half*)smraw;
    __half* sB = sA + 2*ASZ;
    float* stag = (float*)(smraw + STAG_OFF);

    int z = blockIdx.z;
    int set = z % p.nSets; int rest = z / p.nSets;
    int zh = rest % p.Hp, zb = rest / p.Hp;
    const __half* A  = p.A[set]  + zb*p.aSB + zh*p.aSH;
    const __half* Bw = p.Bw[set] + zb*p.bSB + zh*p.bSH;
    const float* bias = p.bias[set];

    int m0 = blockIdx.x*128, n0 = blockIdx.y*64;
    int tid = threadIdx.x, lane = tid&31, wid = tid>>5;
    int wm = wid>>1, wn = wid&1;

    auto prefetch = [&](int kt, int buf) {
        __half* dA = sA + buf*ASZ;
        __half* dB = sB + buf*BSZ;
        #pragma unroll
        for (int i=0;i<4;i++) {                       // A: 128x32 halfs = 512 chunks
            int idx = tid + i*128; int r = idx>>2, c = (idx&3)*8;
            cp16(dA + r*ASTR + c, A + (size_t)(m0+r)*p.lda + kt + c);
        }
        if (TRANSB) {
            #pragma unroll
            for (int i=0;i<2;i++) {                   // B: 64x32 halfs = 256 chunks
                int idx = tid + i*128; int r = idx>>2, c = (idx&3)*8;
                cp16(dB + r*40 + c, Bw + (size_t)(n0+r)*p.ldb + kt + c);
            }
        } else {
            #pragma unroll
            for (int i=0;i<2;i++) {                   // B: 32x64 halfs = 256 chunks
                int idx = tid + i*128; int r = idx>>3, c = (idx&7)*8;
                cp16(dB + r*72 + c, Bw + (size_t)(kt+r)*p.ldb + n0 + c);
            }
        }
        CP_COMMIT();
    };

    wmma::fragment<wmma::accumulator,16,16,16,float> acc[4][2];
    #pragma unroll
    for (int i=0;i<4;i++)
    #pragma unroll
    for (int j=0;j<2;j++) wmma::fill_fragment(acc[i][j], 0.f);

    prefetch(0, 0);
    int nk = p.K/32;
    for (int k=0;k<nk;k++) {
        int cur = k&1;
        if (k+1 < nk) {
            prefetch((k+1)*32, cur^1);
            asm volatile("cp.async.wait_group 1;\n");
        } else {
            asm volatile("cp.async.wait_group 0;\n");
        }
        __syncthreads();
        const __half* cA = sA + cur*ASZ;
        const __half* cB = sB + cur*BSZ;
        #pragma unroll
        for (int kk=0;kk<32;kk+=16) {
            wmma::fragment<wmma::matrix_a,16,16,16,__half,wmma::row_major> af[4];
            #pragma unroll
            for (int i=0;i<4;i++)
                wmma::load_matrix_sync(af[i], cA + (wm*64+16*i)*ASTR + kk, ASTR);
            if (TRANSB) {
                wmma::fragment<wmma::matrix_b,16,16,16,__half,wmma::col_major> bf[2];
                #pragma unroll
                for (int j=0;j<2;j++)
                    wmma::load_matrix_sync(bf[j], cB + (wn*32+16*j)*40 + kk, 40);
                #pragma unroll
                for (int i=0;i<4;i++)
                #pragma unroll
                for (int j=0;j<2;j++) wmma::mma_sync(acc[i][j], af[i], bf[j], acc[i][j]);
            } else {
                wmma::fragment<wmma::matrix_b,16,16,16,__half,wmma::row_major> bf[2];
                #pragma unroll
                for (int j=0;j<2;j++)
                    wmma::load_matrix_sync(bf[j], cB + kk*72 + wn*32 + 16*j, 72);
                #pragma unroll
                for (int i=0;i<4;i++)
                #pragma unroll
                for (int j=0;j<2;j++) wmma::mma_sync(acc[i][j], af[i], bf[j], acc[i][j]);
            }
        }
        __syncthreads();
    }

    float* st = stag + wid*320;
    #pragma unroll
    for (int i=0;i<4;i++)
    #pragma unroll
    for (int j=0;j<2;j++) {
        #pragma unroll
        for (int t=0;t<acc[i][j].num_elements;t++) acc[i][j].x[t] *= p.alpha;
        wmma::store_matrix_sync(st, acc[i][j], 20, wmma::mem_row_major);
        __syncwarp();
        int mb = m0 + wm*64 + i*16;
        int nb = n0 + wn*32 + j*16;
        int r = lane>>1, c0 = (lane&1)*8;
        const float* src = st + r*20 + c0;
        float vv[8];
        #pragma unroll
        for (int t=0;t<8;t++) vv[t] = src[t];
        if (bias) {
            #pragma unroll
            for (int t=0;t<8;t++) vv[t] += bias[nb + c0 + t];
        }
        if (p.resid) {
            const float* rp = p.resid + (size_t)(mb+r)*p.ldc + nb + c0;
            #pragma unroll
            for (int t=0;t<8;t++) vv[t] += rp[t];
        }
        if (OUTH) {
            __half* dst = (__half*)p.C[set] + (zb*p.cSB + zh*p.cSH)
                        + (size_t)(mb+r)*p.ldc + nb + c0;
            __half2 h0 = __floats2half2_rn(vv[0], vv[1]);
            __half2 h1 = __floats2half2_rn(vv[2], vv[3]);
            __half2 h2 = __floats2half2_rn(vv[4], vv[5]);
            __half2 h3 = __floats2half2_rn(vv[6], vv[7]);
            uint4 pack;
            pack.x = *(unsigned*)&h0; pack.y = *(unsigned*)&h1;
            pack.z = *(unsigned*)&h2; pack.w = *(unsigned*)&h3;
            *(uint4*)dst = pack;
        } else {
            float* dst = (float*)p.C[set] + (zb*p.cSB + zh*p.cSH)
                       + (size_t)(mb+r)*p.ldc + nb + c0;
            *(float4*)(dst)   = make_float4(vv[0],vv[1],vv[2],vv[3]);
            *(float4*)(dst+4) = make_float4(vv[4],vv[5],vv[6],vv[7]);
        }
        __syncwarp();
    }
}

// ---------------- small GEMM for cond (N=72), tf32 inline ----------------
__global__ __launch_bounds__(256) void gemm_s(
    const float* __restrict__ A, const float* __restrict__ Bw,
    const float* __restrict__ bias, float* __restrict__ C, int N, int K)
{
    constexpr int BN = 64;
    __shared__ float sA[128*36];
    __shared__ float sB[32*68];
    __shared__ float stag[8][16*20];
    int m0 = blockIdx.x*128, n0 = blockIdx.y*BN;
    int tid = threadIdx.x, lane = tid&31, wid = tid>>5;
    int wm = wid>>1, wn = wid&1;

    wmma::fragment<wmma::accumulator,16,16,8,float> acc[2][2];
    #pragma unroll
    for (int i=0;i<2;i++)
    #pragma unroll
    for (int j=0;j<2;j++) wmma::fill_fragment(acc[i][j], 0.f);

    for (int kt=0; kt<K; kt+=32) {
        __syncthreads();
        #pragma unroll
        for (int i=0;i<4;i++) {
            int idx = tid + i*256; int r = idx>>3, c = (idx&7)*4;
            float4 v = *(const float4*)(A + (size_t)(m0+r)*K + kt + c);
            v.x = wmma::__float_to_tf32(v.x); v.y = wmma::__float_to_tf32(v.y);
            v.z = wmma::__float_to_tf32(v.z); v.w = wmma::__float_to_tf32(v.w);
            *(float4*)(sA + r*36 + c) = v;
        }
        #pragma unroll
        for (int i=0;i<2;i++) {
            int idx = tid + i*256; int r = idx>>4, c = (idx&15)*4;
            const float* bp = Bw + (size_t)(kt+r)*N + n0 + c;
            float4 v;
            v.x = (n0+c+0<N)? bp[0]:0.f; v.y = (n0+c+1<N)? bp[1]:0.f;
            v.z = (n0+c+2<N)? bp[2]:0.f; v.w = (n0+c+3<N)? bp[3]:0.f;
            v.x = wmma::__float_to_tf32(v.x); v.y = wmma::__float_to_tf32(v.y);
            v.z = wmma::__float_to_tf32(v.z); v.w = wmma::__float_to_tf32(v.w);
            *(float4*)(sB + r*68 + c) = v;
        }
        __syncthreads();
        #pragma unroll
        for (int kk=0;kk<32;kk+=8) {
            wmma::fragment<wmma::matrix_a,16,16,8,wmma::precision::tf32,wmma::row_major> af[2];
            #pragma unroll
            for (int i=0;i<2;i++)
                wmma::load_matrix_sync(af[i], sA + (wm*32+16*i)*36 + kk, 36);
            wmma::fragment<wmma::matrix_b,16,16,8,wmma::precision::tf32,wmma::row_major> bf[2];
            #pragma unroll
            for (int j=0;j<2;j++)
                wmma::load_matrix_sync(bf[j], sB + kk*68 + wn*32 + 16*j, 68);
            #pragma unroll
            for (int i=0;i<2;i++)
            #pragma unroll
            for (int j=0;j<2;j++) wmma::mma_sync(acc[i][j], af[i], bf[j], acc[i][j]);
        }
    }
    #pragma unroll
    for (int i=0;i<2;i++)
    #pragma unroll
    for (int j=0;j<2;j++) {
        wmma::store_matrix_sync(stag[wid], acc[i][j], 20, wmma::mem_row_major);
        __syncwarp();
        int mb = m0 + wm*32 + i*16;
        int nb = n0 + wn*32 + j*16;
        int r = lane>>1, c0 = (lane&1)*8;
        const float* src = stag[wid] + r*20 + c0;
        #pragma unroll
        for (int t=0;t<8;t++) {
            int n = nb + c0 + t;
            if (n < N) C[(size_t)(mb+r)*N + n] = src[t] + bias[n];
        }
        __syncwarp();
    }
}

// ---------------- fused spatial-gate + softmax: warp-per-head ----------------
__global__ __launch_bounds__(384) void fuse_softmax_k(
    const float* __restrict__ ploc, const void* __restrict__ maskp,
    float* __restrict__ P)
{
    int bl = blockIdx.x; int b = bl >> 9; int l = bl & 511;
    __shared__ float splcT[5*512];
    __shared__ unsigned char smask[512];
    int tid = threadIdx.x, lane = tid&31, h = tid>>5;

    const float* pl = ploc + (size_t)bl*2560;
    for (int i=tid; i<2560; i+=384) {
        int t = i/5, d = i%5;
        splcT[d*512 + t] = pl[i];
    }
    int mode = g_mask_mode;
    for (int i=tid; i<512; i+=384)
        smask[i] = (unsigned char)is_masked(maskp, b*L_ + i, mode);
    __syncthreads();

    const float* swp = g_sw + (size_t)bl*72 + h*6;
    float c0=swp[0], c1=swp[1], c2=swp[2], c3=swp[3], c4=swp[4], c5=swp[5];
    float* Srow = P + (((size_t)b*H_ + h)*L_ + l)*L_;
    __half* Ph = g_Ph + (((size_t)b*H_ + h)*L_ + l)*L_;

    float4 xv[4];
    float mx = -INFINITY;
    #pragma unroll
    for (int j=0;j<4;j++) {
        int t = j*128 + lane*4;
        float4 sv = *(const float4*)(Srow + t);
        float4 p0 = *(const float4*)(splcT + 0*512 + t);
        float4 p1 = *(const float4*)(splcT + 1*512 + t);
        float4 p2 = *(const float4*)(splcT + 2*512 + t);
        float4 p3 = *(const float4*)(splcT + 3*512 + t);
        float4 p4 = *(const float4*)(splcT + 4*512 + t);
        uchar4 mk = *(const uchar4*)(smask + t);
        float4 r;
        {
            float loc = c0 + c1*p0.x + c2*p1.x + c3*p2.x + c4*p3.x + c5*p4.x;
            float sg = 1.f/(1.f+__expf(-loc));
            r.x = mk.x ? -INFINITY : sv.x + __logf(fmaxf(sg,1e-6f));
        }
        {
            float loc = c0 + c1*p0.y + c2*p1.y + c3*p2.y + c4*p3.y + c5*p4.y;
            float sg = 1.f/(1.f+__expf(-loc));
            r.y = mk.y ? -INFINITY : sv.y + __logf(fmaxf(sg,1e-6f));
        }
        {
            float loc = c0 + c1*p0.z + c2*p1.z + c3*p2.z + c4*p3.z + c5*p4.z;
            float sg = 1.f/(1.f+__expf(-loc));
            r.z = mk.z ? -INFINITY : sv.z + __logf(fmaxf(sg,1e-6f));
        }
        {
            float loc = c0 + c1*p0.w + c2*p1.w + c3*p2.w + c4*p3.w + c5*p4.w;
            float sg = 1.f/(1.f+__expf(-loc));
            r.w = mk.w ? -INFINITY : sv.w + __logf(fmaxf(sg,1e-6f));
        }
        xv[j] = r;
        mx = fmaxf(mx, fmaxf(fmaxf(r.x,r.y), fmaxf(r.z,r.w)));
    }
    #pragma unroll
    for (int o=16;o;o>>=1) mx = fmaxf(mx, __shfl_xor_sync(~0u, mx, o));
    float s = 0.f;
    #pragma unroll
    for (int j=0;j<4;j++) {
        float4 r = xv[j];
        r.x = (r.x == -INFINITY) ? 0.f : __expf(r.x - mx);
        r.y = (r.y == -INFINITY) ? 0.f : __expf(r.y - mx);
        r.z = (r.z == -INFINITY) ? 0.f : __expf(r.z - mx);
        r.w = (r.w == -INFINITY) ? 0.f : __expf(r.w - mx);
        xv[j] = r;
        s += r.x + r.y + r.z + r.w;
    }
    #pragma unroll
    for (int o=16;o;o>>=1) s += __shfl_xor_sync(~0u, s, o);
    float inv = 1.f/s;
    #pragma unroll
    for (int j=0;j<4;j++) {
        int t = j*128 + lane*4;
        float4 r = xv[j];
        r.x *= inv; r.y *= inv; r.z *= inv; r.w *= inv;
        *(float4*)(Srow + t) = r;
        __half2 h01 = __floats2half2_rn(r.x, r.y);
        __half2 h23 = __floats2half2_rn(r.z, r.w);
        *(__half2*)(Ph + t)     = h01;
        *(__half2*)(Ph + t + 2) = h23;
    }
}

// ---------------- LayerNorm ----------------
__global__ __launch_bounds__(256) void ln_k(
    const float* __restrict__ sc, const float* __restrict__ bs, float* __restrict__ Y)
{
    int row = blockIdx.x;
    const float* x = g_x + (size_t)row*D_;
    float* y = Y + (size_t)row*D_;
    __shared__ float r1[8], r2[8];
    int tid = threadIdx.x;
    float v0=x[tid], v1=x[tid+256], v2=x[tid+512];
    float s = v0+v1+v2, q = v0*v0+v1*v1+v2*v2;
    #pragma unroll
    for (int o=16;o;o>>=1) {
        s += __shfl_xor_sync(~0u, s, o);
        q += __shfl_xor_sync(~0u, q, o);
    }
    if ((tid&31)==0) { r1[tid>>5]=s; r2[tid>>5]=q; }
    __syncthreads();
    s = r1[0]+r1[1]+r1[2]+r1[3]+r1[4]+r1[5]+r1[6]+r1[7];
    q = r2[0]+r2[1]+r2[2]+r2[3]+r2[4]+r2[5]+r2[6]+r2[7];
    float mu = s * (1.f/D_);
    float var = q * (1.f/D_) - mu*mu;
    float r = rsqrtf(var + 1e-5f);
    y[tid]     = (v0-mu)*r*sc[tid]     + bs[tid];
    y[tid+256] = (v1-mu)*r*sc[tid+256] + bs[tid+256];
    y[tid+512] = (v2-mu)*r*sc[tid+512] + bs[tid+512];
}

// ---------------- host ----------------
extern "C" void kernel_launch(void* const* d_in, const int* in_sizes, int n_in,
                              void* d_out, int out_size) {
    const float* q    = (const float*)d_in[0];
    const float* k    = (const float*)d_in[1];
    const float* v    = (const float*)d_in[2];
    const float* ploc = (const float*)d_in[3];
    const float* txt  = (const float*)d_in[4];
    const void*  mask = d_in[5];
    const float* Wq = (const float*)d_in[6],  *bq = (const float*)d_in[7];
    const float* Wk = (const float*)d_in[8],  *bk = (const float*)d_in[9];
    const float* Wv = (const float*)d_in[10], *bv = (const float*)d_in[11];
    const float* Wfc= (const float*)d_in[12], *bfc= (const float*)d_in[13];
    const float* Wc = (const float*)d_in[14], *bc = (const float*)d_in[15];
    const float* lns= (const float*)d_in[16], *lnb= (const float*)d_in[17];

    float* y = (float*)d_out;
    float* P = y + (size_t)B_*L_*D_;

    void *a0,*a1,*a2,*a3,*a4,*a5,*a6,*a7,*a8,*a9,*aa,*ab,*ac,*ad,*ae;
    cudaGetSymbolAddress(&a0, g_qch);  cudaGetSymbolAddress(&a1, g_kch);
    cudaGetSymbolAddress(&a2, g_vch);  cudaGetSymbolAddress(&a3, g_Wqh);
    cudaGetSymbolAddress(&a4, g_Wkh);  cudaGetSymbolAddress(&a5, g_Wvh);
    cudaGetSymbolAddress(&a6, g_Wfch); cudaGetSymbolAddress(&a7, g_qhh);
    cudaGetSymbolAddress(&a8, g_khh);  cudaGetSymbolAddress(&a9, g_vhh);
    cudaGetSymbolAddress(&aa, g_ctxh); cudaGetSymbolAddress(&ab, g_Ph);
    cudaGetSymbolAddress(&ac, g_qt);   cudaGetSymbolAddress(&ad, g_x);
    cudaGetSymbolAddress(&ae, g_sw);
    __half *qch=(__half*)a0, *kch=(__half*)a1, *vch=(__half*)a2;
    __half *Wqh=(__half*)a3, *Wkh=(__half*)a4, *Wvh=(__half*)a5, *Wfch=(__half*)a6;
    __half *qhh=(__half*)a7, *khh=(__half*)a8, *vhh=(__half*)a9;
    __half *ctxh=(__half*)aa, *Ph=(__half*)ab;
    float *qt=(float*)ac, *xx=(float*)ad, *sw=(float*)ae;

    const int M = B_*L_;
    const int NQ = M*D_, NW = D_*D_;
    constexpr int GS = 36864;
    cudaFuncSetAttribute(gemm_h<false,true>,  cudaFuncAttributeMaxDynamicSharedMemorySize, GS);
    cudaFuncSetAttribute(gemm_h<false,false>, cudaFuncAttributeMaxDynamicSharedMemorySize, GS);
    cudaFuncSetAttribute(gemm_h<true,false>,  cudaFuncAttributeMaxDynamicSharedMemorySize, GS);

    detect_mask_k<<<1,256>>>((const unsigned int*)mask);

    { // float -> half: q,k,v + Wq,Wk,Wv,Wfc
        ConvP cp{};
        cp.src[0]=q;   cp.dst[0]=qch;  cp.n[0]=NQ;
        cp.src[1]=k;   cp.dst[1]=kch;  cp.n[1]=NQ;
        cp.src[2]=v;   cp.dst[2]=vch;  cp.n[2]=NQ;
        cp.src[3]=Wq;  cp.dst[3]=Wqh;  cp.n[3]=NW;
        cp.src[4]=Wk;  cp.dst[4]=Wkh;  cp.n[4]=NW;
        cp.src[5]=Wv;  cp.dst[5]=Wvh;  cp.n[5]=NW;
        cp.src[6]=Wfc; cp.dst[6]=Wfch; cp.n[6]=NW;
        conv_k<<<dim3(NQ/1024, 7), 256>>>(cp);
    }
    add_txt_k<<<(NQ + 255)/256, 256>>>(q, txt);

    { // Q/K/V projections -> half outputs
        GemmHP g{};
        g.A[0]=qch; g.A[1]=kch; g.A[2]=vch;
        g.Bw[0]=Wqh; g.Bw[1]=Wkh; g.Bw[2]=Wvh;
        g.bias[0]=bq; g.bias[1]=bk; g.bias[2]=bv;
        g.C[0]=qhh; g.C[1]=khh; g.C[2]=vhh;
        g.N=D_; g.K=D_; g.lda=D_; g.ldb=D_; g.ldc=D_;
        g.nSets=3; g.Hp=1; g.alpha=1.f;
        gemm_h<false,true><<<dim3(M/128, D_/64, 3), 128, GS>>>(g);
    }
    { // cond (tf32)
        gemm_s<<<dim3(M/128, 2, 1), 256>>>(qt, Wc, bc, sw, 72, D_);
    }
    { // S = 0.125 * Q @ K^T -> P fp32
        GemmHP g{};
        g.A[0]=qhh; g.Bw[0]=khh; g.C[0]=P;
        g.N=L_; g.K=64; g.lda=D_; g.ldb=D_; g.ldc=L_;
        g.aSB=(long long)L_*D_; g.aSH=64;
        g.bSB=(long long)L_*D_; g.bSH=64;
        g.cSB=(long long)H_*L_*L_; g.cSH=(long long)L_*L_;
        g.nSets=1; g.Hp=H_; g.alpha=0.125f;
        gemm_h<true,false><<<dim3(L_/128, L_/64, B_*H_), 128, GS>>>(g);
    }
    fuse_softmax_k<<<M, 384>>>(ploc, mask, P);
    { // ctx = P @ V -> half
        GemmHP g{};
        g.A[0]=Ph; g.Bw[0]=vhh; g.C[0]=ctxh;
        g.N=64; g.K=L_; g.lda=L_; g.ldb=D_; g.ldc=D_;
        g.aSB=(long long)H_*L_*L_; g.aSH=(long long)L_*L_;
        g.bSB=(long long)L_*D_; g.bSH=64;
        g.cSB=(long long)L_*D_; g.cSH=64;
        g.nSets=1; g.Hp=H_; g.alpha=1.f;
        gemm_h<false,true><<<dim3(L_/128, 1, B_*H_), 128, GS>>>(g);
    }
    { // x = ctx @ Wfc + bfc + q (fp32 out)
        GemmHP g{};
        g.A[0]=ctxh; g.Bw[0]=Wfch; g.bias[0]=bfc; g.C[0]=xx;
        g.resid=q; g.N=D_; g.K=D_; g.lda=D_; g.ldb=D_; g.ldc=D_;
        g.nSets=1; g.Hp=1; g.alpha=1.f;
        gemm_h<false,false><<<dim3(M/128, D_/64, 1), 128, GS>>>(g);
    }
    ln_k<<<M, 256>>>(lns, lnb, y);
}

// round 12
// speedup vs baseline: 3.3122x; 1.0509x over previous
#include <cuda_runtime.h>
#include <cuda_fp16.h>
#include <mma.h>
#include <cstdint>
#include <cstddef>

using namespace nvcuda;

#define B_ 32
#define L_ 512
#define D_ 768
#define H_ 12

// ---------------- scratch ----------------
__device__ __half g_qch[(size_t)B_*L_*D_];
__device__ __half g_kch[(size_t)B_*L_*D_];
__device__ __half g_vch[(size_t)B_*L_*D_];
__device__ __half g_Wqh[D_*D_];
__device__ __half g_Wkh[D_*D_];
__device__ __half g_Wvh[D_*D_];
__device__ __half g_Wfch[D_*D_];
__device__ __half g_Wch[D_*72];
__device__ __half g_qth[(size_t)B_*L_*D_];
__device__ __half g_qhh[(size_t)B_*L_*D_];
__device__ __half g_khh[(size_t)B_*L_*D_];
__device__ __half g_vhh[(size_t)B_*L_*D_];
__device__ __half g_ctxh[(size_t)B_*L_*D_];
__device__ __half g_Ph[(size_t)B_*H_*L_*L_];
__device__ float  g_x[(size_t)B_*L_*D_];
__device__ float  g_sw[(size_t)B_*L_*72];
__device__ int    g_mask_mode;

// ---------------- cp.async ----------------
__device__ __forceinline__ void cp16(void* s, const void* g) {
    unsigned a = (unsigned)__cvta_generic_to_shared(s);
    asm volatile("cp.async.cg.shared.global [%0], [%1], 16;\n" :: "r"(a), "l"(g));
}
__device__ __forceinline__ void cp16z(void* s, const void* g, int sb) {
    unsigned a = (unsigned)__cvta_generic_to_shared(s);
    asm volatile("cp.async.cg.shared.global [%0], [%1], 16, %2;\n" :: "r"(a), "l"(g), "r"(sb));
}
#define CP_COMMIT() asm volatile("cp.async.commit_group;\n")

// ---------------- mask dtype detection ----------------
__global__ void detect_mask_k(const unsigned int* __restrict__ w) {
    __shared__ int sF, sO;
    if (threadIdx.x == 0) { sF = 0; sO = 0; }
    __syncthreads();
    int f = 0, o = 0;
    for (int i = threadIdx.x; i < 4096; i += 256) {
        unsigned v = w[i];
        if (v == 0x3F800000u) f = 1;
        else if (v > 1u) o = 1;
    }
    if (f) atomicOr(&sF, 1);
    if (o) atomicOr(&sO, 1);
    __syncthreads();
    if (threadIdx.x == 0) g_mask_mode = sF ? 1 : (sO ? 2 : 0);
}

__device__ __forceinline__ int is_masked(const void* mp, int idx, int mode) {
    if (mode == 2) return ((const unsigned char*)mp)[idx] != 0;
    if (mode == 1) return ((const float*)mp)[idx] != 0.0f;
    return ((const int*)mp)[idx] != 0;
}

// ---------------- float -> half conversion ----------------
struct ConvP { const float* src[8]; __half* dst[8]; int n[8]; };
__global__ void conv_k(ConvP p) {
    int s = blockIdx.y;
    int i = (blockIdx.x * 256 + threadIdx.x) * 4;
    if (i >= p.n[s]) return;
    float4 v = *(const float4*)(p.src[s] + i);
    __half2 h01 = __floats2half2_rn(v.x, v.y);
    __half2 h23 = __floats2half2_rn(v.z, v.w);
    *(__half2*)(p.dst[s] + i)     = h01;
    *(__half2*)(p.dst[s] + i + 2) = h23;
}

// ---------------- qt(half) = q + txt ----------------
__global__ void add_txt_k(const float* __restrict__ q, const float* __restrict__ txt) {
    size_t idx = (size_t)blockIdx.x * 256 + threadIdx.x;
    if (idx >= (size_t)B_*L_*D_) return;
    int b = (int)(idx / ((size_t)L_*D_));
    int c = (int)(idx % D_);
    g_qth[idx] = __float2half_rn(q[idx] + txt[b*D_ + c]);
}

// ---------------- fp16 pipelined GEMM ----------------
// BM=128, BN=32*NF, BK=32; 4 warps (2x2), warp tile 64 x (16*NF)
struct GemmHP {
    const __half* A[3]; const __half* Bw[3]; const float* bias[3];
    void* C[3];
    const float* resid;
    int N, K, lda, ldb, ldc, nSets, Hp;
    long long aSB, aSH, bSB, bSH, cSB, cSH;
    float alpha;
};

template<bool TRANSB, bool OUTH, int NF, int MINB, bool BOUND>
__global__ __launch_bounds__(128, MINB) void gemm_h(GemmHP p)
{
    constexpr int BN   = 32*NF;
    constexpr int ASTR = 40;
    constexpr int ASZ  = 128*ASTR;                     // halfs
    constexpr int BSTR = TRANSB ? 40 : (BN + 8);
    constexpr int BSZ  = TRANSB ? BN*40 : 32*(BN+8);   // halfs
    constexpr int SOFF = (2*ASZ + 2*BSZ)*2;            // bytes
    extern __shared__ char smraw[];
    __half* sA = (__half*)smraw;
    __half* sB = sA + 2*ASZ;
    float* stag = (float*)(smraw + SOFF);

    int z = blockIdx.z;
    int set = z % p.nSets; int rest = z / p.nSets;
    int zh = rest % p.Hp, zb = rest / p.Hp;
    const __half* A  = p.A[set]  + zb*p.aSB + zh*p.aSH;
    const __half* Bw = p.Bw[set] + zb*p.bSB + zh*p.bSH;
    const float* bias = p.bias[set];

    int m0 = blockIdx.x*128, n0 = blockIdx.y*BN;
    int tid = threadIdx.x, lane = tid&31, wid = tid>>5;
    int wm = wid>>1, wn = wid&1;

    auto prefetch = [&](int kt, int buf) {
        __half* dA = sA + buf*ASZ;
        __half* dB = sB + buf*BSZ;
        #pragma unroll
        for (int i=0;i<4;i++) {                       // A: 128x32 halfs
            int idx = tid + i*128; int r = idx>>2, c = (idx&3)*8;
            cp16(dA + r*ASTR + c, A + (size_t)(m0+r)*p.lda + kt + c);
        }
        if (TRANSB) {
            #pragma unroll
            for (int i=0;i<NF;i++) {                  // B: BN x 32 halfs
                int idx = tid + i*128; int r = idx>>2, c = (idx&3)*8;
                cp16(dB + r*40 + c, Bw + (size_t)(n0+r)*p.ldb + kt + c);
            }
        } else {
            #pragma unroll
            for (int i=0;i<NF;i++) {                  // B: 32 x BN halfs
                int idx = tid + i*128;
                int r = idx/(BN/8), c = (idx%(BN/8))*8;
                if (BOUND) {
                    int sb = (n0 + c + 8 <= p.N) ? 16 : 0;
                    cp16z(dB + r*BSTR + c, Bw + (size_t)(kt+r)*p.ldb + n0 + c, sb);
                } else {
                    cp16(dB + r*BSTR + c, Bw + (size_t)(kt+r)*p.ldb + n0 + c);
                }
            }
        }
        CP_COMMIT();
    };

    wmma::fragment<wmma::accumulator,16,16,16,float> acc[4][NF];
    #pragma unroll
    for (int i=0;i<4;i++)
    #pragma unroll
    for (int j=0;j<NF;j++) wmma::fill_fragment(acc[i][j], 0.f);

    prefetch(0, 0);
    int nk = p.K/32;
    for (int k=0;k<nk;k++) {
        int cur = k&1;
        if (k+1 < nk) {
            prefetch((k+1)*32, cur^1);
            asm volatile("cp.async.wait_group 1;\n");
        } else {
            asm volatile("cp.async.wait_group 0;\n");
        }
        __syncthreads();
        const __half* cA = sA + cur*ASZ;
        const __half* cB = sB + cur*BSZ;
        #pragma unroll
        for (int kk=0;kk<32;kk+=16) {
            wmma::fragment<wmma::matrix_a,16,16,16,__half,wmma::row_major> af[4];
            #pragma unroll
            for (int i=0;i<4;i++)
                wmma::load_matrix_sync(af[i], cA + (wm*64+16*i)*ASTR + kk, ASTR);
            if (TRANSB) {
                wmma::fragment<wmma::matrix_b,16,16,16,__half,wmma::col_major> bf[NF];
                #pragma unroll
                for (int j=0;j<NF;j++)
                    wmma::load_matrix_sync(bf[j], cB + (wn*16*NF+16*j)*40 + kk, 40);
                #pragma unroll
                for (int i=0;i<4;i++)
                #pragma unroll
                for (int j=0;j<NF;j++) wmma::mma_sync(acc[i][j], af[i], bf[j], acc[i][j]);
            } else {
                wmma::fragment<wmma::matrix_b,16,16,16,__half,wmma::row_major> bf[NF];
                #pragma unroll
                for (int j=0;j<NF;j++)
                    wmma::load_matrix_sync(bf[j], cB + kk*BSTR + wn*NF*16 + 16*j, BSTR);
                #pragma unroll
                for (int i=0;i<4;i++)
                #pragma unroll
                for (int j=0;j<NF;j++) wmma::mma_sync(acc[i][j], af[i], bf[j], acc[i][j]);
            }
        }
        __syncthreads();
    }

    float* st = stag + wid*320;
    #pragma unroll
    for (int i=0;i<4;i++)
    #pragma unroll
    for (int j=0;j<NF;j++) {
        #pragma unroll
        for (int t=0;t<acc[i][j].num_elements;t++) acc[i][j].x[t] *= p.alpha;
        wmma::store_matrix_sync(st, acc[i][j], 20, wmma::mem_row_major);
        __syncwarp();
        int mb = m0 + wm*64 + i*16;
        int nb = n0 + wn*NF*16 + j*16;
        int r = lane>>1, c0 = (lane&1)*8;
        const float* src = st + r*20 + c0;
        if (BOUND) {
            #pragma unroll
            for (int t=0;t<8;t++) {
                int n = nb + c0 + t;
                if (n < p.N) {
                    float vv = src[t];
                    if (bias) vv += bias[n];
                    if (OUTH) {
                        __half* dst = (__half*)p.C[set] + (zb*p.cSB + zh*p.cSH)
                                    + (size_t)(mb+r)*p.ldc + n;
                        *dst = __float2half_rn(vv);
                    } else {
                        float* dst = (float*)p.C[set] + (zb*p.cSB + zh*p.cSH)
                                   + (size_t)(mb+r)*p.ldc + n;
                        *dst = vv;
                    }
                }
            }
        } else {
            float vv[8];
            #pragma unroll
            for (int t=0;t<8;t++) vv[t] = src[t];
            if (bias) {
                #pragma unroll
                for (int t=0;t<8;t++) vv[t] += bias[nb + c0 + t];
            }
            if (p.resid) {
                const float* rp = p.resid + (size_t)(mb+r)*p.ldc + nb + c0;
                #pragma unroll
                for (int t=0;t<8;t++) vv[t] += rp[t];
            }
            if (OUTH) {
                __half* dst = (__half*)p.C[set] + (zb*p.cSB + zh*p.cSH)
                            + (size_t)(mb+r)*p.ldc + nb + c0;
                __half2 h0 = __floats2half2_rn(vv[0], vv[1]);
                __half2 h1 = __floats2half2_rn(vv[2], vv[3]);
                __half2 h2 = __floats2half2_rn(vv[4], vv[5]);
                __half2 h3 = __floats2half2_rn(vv[6], vv[7]);
                uint4 pack;
                pack.x = *(unsigned*)&h0; pack.y = *(unsigned*)&h1;
                pack.z = *(unsigned*)&h2; pack.w = *(unsigned*)&h3;
                *(uint4*)dst = pack;
            } else {
                float* dst = (float*)p.C[set] + (zb*p.cSB + zh*p.cSH)
                           + (size_t)(mb+r)*p.ldc + nb + c0;
                *(float4*)(dst)   = make_float4(vv[0],vv[1],vv[2],vv[3]);
                *(float4*)(dst+4) = make_float4(vv[4],vv[5],vv[6],vv[7]);
            }
        }
        __syncwarp();
    }
}

// ---------------- fused spatial-gate + softmax: warp-per-head ----------------
__global__ __launch_bounds__(384) void fuse_softmax_k(
    const float* __restrict__ ploc, const void* __restrict__ maskp,
    float* __restrict__ P)
{
    int bl = blockIdx.x; int b = bl >> 9; int l = bl & 511;
    __shared__ float splcT[5*512];
    __shared__ unsigned char smask[512];
    int tid = threadIdx.x, lane = tid&31, h = tid>>5;

    const float* pl = ploc + (size_t)bl*2560;
    for (int i=tid; i<2560; i+=384) {
        int t = i/5, d = i%5;
        splcT[d*512 + t] = pl[i];
    }
    int mode = g_mask_mode;
    for (int i=tid; i<512; i+=384)
        smask[i] = (unsigned char)is_masked(maskp, b*L_ + i, mode);
    __syncthreads();

    const float* swp = g_sw + (size_t)bl*72 + h*6;
    float c0=swp[0], c1=swp[1], c2=swp[2], c3=swp[3], c4=swp[4], c5=swp[5];
    float* Srow = P + (((size_t)b*H_ + h)*L_ + l)*L_;
    __half* Ph = g_Ph + (((size_t)b*H_ + h)*L_ + l)*L_;

    float4 xv[4];
    float mx = -INFINITY;
    #pragma unroll
    for (int j=0;j<4;j++) {
        int t = j*128 + lane*4;
        float4 sv = *(const float4*)(Srow + t);
        float4 p0 = *(const float4*)(splcT + 0*512 + t);
        float4 p1 = *(const float4*)(splcT + 1*512 + t);
        float4 p2 = *(const float4*)(splcT + 2*512 + t);
        float4 p3 = *(const float4*)(splcT + 3*512 + t);
        float4 p4 = *(const float4*)(splcT + 4*512 + t);
        uchar4 mk = *(const uchar4*)(smask + t);
        float4 r;
        {
            float loc = c0 + c1*p0.x + c2*p1.x + c3*p2.x + c4*p3.x + c5*p4.x;
            float sg = 1.f/(1.f+__expf(-loc));
            r.x = mk.x ? -INFINITY : sv.x + __logf(fmaxf(sg,1e-6f));
        }
        {
            float loc = c0 + c1*p0.y + c2*p1.y + c3*p2.y + c4*p3.y + c5*p4.y;
            float sg = 1.f/(1.f+__expf(-loc));
            r.y = mk.y ? -INFINITY : sv.y + __logf(fmaxf(sg,1e-6f));
        }
        {
            float loc = c0 + c1*p0.z + c2*p1.z + c3*p2.z + c4*p3.z + c5*p4.z;
            float sg = 1.f/(1.f+__expf(-loc));
            r.z = mk.z ? -INFINITY : sv.z + __logf(fmaxf(sg,1e-6f));
        }
        {
            float loc = c0 + c1*p0.w + c2*p1.w + c3*p2.w + c4*p3.w + c5*p4.w;
            float sg = 1.f/(1.f+__expf(-loc));
            r.w = mk.w ? -INFINITY : sv.w + __logf(fmaxf(sg,1e-6f));
        }
        xv[j] = r;
        mx = fmaxf(mx, fmaxf(fmaxf(r.x,r.y), fmaxf(r.z,r.w)));
    }
    #pragma unroll
    for (int o=16;o;o>>=1) mx = fmaxf(mx, __shfl_xor_sync(~0u, mx, o));
    float s = 0.f;
    #pragma unroll
    for (int j=0;j<4;j++) {
        float4 r = xv[j];
        r.x = (r.x == -INFINITY) ? 0.f : __expf(r.x - mx);
        r.y = (r.y == -INFINITY) ? 0.f : __expf(r.y - mx);
        r.z = (r.z == -INFINITY) ? 0.f : __expf(r.z - mx);
        r.w = (r.w == -INFINITY) ? 0.f : __expf(r.w - mx);
        xv[j] = r;
        s += r.x + r.y + r.z + r.w;
    }
    #pragma unroll
    for (int o=16;o;o>>=1) s += __shfl_xor_sync(~0u, s, o);
    float inv = 1.f/s;
    #pragma unroll
    for (int j=0;j<4;j++) {
        int t = j*128 + lane*4;
        float4 r = xv[j];
        r.x *= inv; r.y *= inv; r.z *= inv; r.w *= inv;
        *(float4*)(Srow + t) = r;
        __half2 h01 = __floats2half2_rn(r.x, r.y);
        __half2 h23 = __floats2half2_rn(r.z, r.w);
        *(__half2*)(Ph + t)     = h01;
        *(__half2*)(Ph + t + 2) = h23;
    }
}

// ---------------- LayerNorm ----------------
__global__ __launch_bounds__(256) void ln_k(
    const float* __restrict__ sc, const float* __restrict__ bs, float* __restrict__ Y)
{
    int row = blockIdx.x;
    const float* x = g_x + (size_t)row*D_;
    float* y = Y + (size_t)row*D_;
    __shared__ float r1[8], r2[8];
    int tid = threadIdx.x;
    float v0=x[tid], v1=x[tid+256], v2=x[tid+512];
    float s = v0+v1+v2, q = v0*v0+v1*v1+v2*v2;
    #pragma unroll
    for (int o=16;o;o>>=1) {
        s += __shfl_xor_sync(~0u, s, o);
        q += __shfl_xor_sync(~0u, q, o);
    }
    if ((tid&31)==0) { r1[tid>>5]=s; r2[tid>>5]=q; }
    __syncthreads();
    s = r1[0]+r1[1]+r1[2]+r1[3]+r1[4]+r1[5]+r1[6]+r1[7];
    q = r2[0]+r2[1]+r2[2]+r2[3]+r2[4]+r2[5]+r2[6]+r2[7];
    float mu = s * (1.f/D_);
    float var = q * (1.f/D_) - mu*mu;
    float r = rsqrtf(var + 1e-5f);
    y[tid]     = (v0-mu)*r*sc[tid]     + bs[tid];
    y[tid+256] = (v1-mu)*r*sc[tid+256] + bs[tid+256];
    y[tid+512] = (v2-mu)*r*sc[tid+512] + bs[tid+512];
}

// ---------------- host ----------------
extern "C" void kernel_launch(void* const* d_in, const int* in_sizes, int n_in,
                              void* d_out, int out_size) {
    const float* q    = (const float*)d_in[0];
    const float* k    = (const float*)d_in[1];
    const float* v    = (const float*)d_in[2];
    const float* ploc = (const float*)d_in[3];
    const float* txt  = (const float*)d_in[4];
    const void*  mask = d_in[5];
    const float* Wq = (const float*)d_in[6],  *bq = (const float*)d_in[7];
    const float* Wk = (const float*)d_in[8],  *bk = (const float*)d_in[9];
    const float* Wv = (const float*)d_in[10], *bv = (const float*)d_in[11];
    const float* Wfc= (const float*)d_in[12], *bfc= (const float*)d_in[13];
    const float* Wc = (const float*)d_in[14], *bc = (const float*)d_in[15];
    const float* lns= (const float*)d_in[16], *lnb= (const float*)d_in[17];

    float* y = (float*)d_out;
    float* P = y + (size_t)B_*L_*D_;

    void *a0,*a1,*a2,*a3,*a4,*a5,*a6,*a7,*a8,*a9,*aa,*ab,*ac,*ad,*ae,*af_;
    cudaGetSymbolAddress(&a0, g_qch);  cudaGetSymbolAddress(&a1, g_kch);
    cudaGetSymbolAddress(&a2, g_vch);  cudaGetSymbolAddress(&a3, g_Wqh);
    cudaGetSymbolAddress(&a4, g_Wkh);  cudaGetSymbolAddress(&a5, g_Wvh);
    cudaGetSymbolAddress(&a6, g_Wfch); cudaGetSymbolAddress(&a7, g_qhh);
    cudaGetSymbolAddress(&a8, g_khh);  cudaGetSymbolAddress(&a9, g_vhh);
    cudaGetSymbolAddress(&aa, g_ctxh); cudaGetSymbolAddress(&ab, g_Ph);
    cudaGetSymbolAddress(&ac, g_qth);  cudaGetSymbolAddress(&ad, g_x);
    cudaGetSymbolAddress(&ae, g_sw);   cudaGetSymbolAddress(&af_, g_Wch);
    __half *qch=(__half*)a0, *kch=(__half*)a1, *vch=(__half*)a2;
    __half *Wqh=(__half*)a3, *Wkh=(__half*)a4, *Wvh=(__half*)a5, *Wfch=(__half*)a6;
    __half *qhh=(__half*)a7, *khh=(__half*)a8, *vhh=(__half*)a9;
    __half *ctxh=(__half*)aa, *Ph=(__half*)ab, *qth=(__half*)ac, *Wch=(__half*)af_;
    float *xx=(float*)ad, *sw=(float*)ae;

    const int M = B_*L_;
    const int NQ = M*D_, NW = D_*D_;
    // smem sizes (bytes): A halfs 2*5120, B halfs per variant, + 4*320 floats stag
    constexpr int GS_N4 = (2*5120 + 2*(32*136))*2 + 4*320*4;   // 43008
    constexpr int GS_T4 = (2*5120 + 2*(128*40))*2 + 4*320*4;   // 46080
    constexpr int GS_N2 = (2*5120 + 2*(32*72))*2  + 4*320*4;   // 34816
    cudaFuncSetAttribute((const void*)gemm_h<false,true,4,2,false>,  cudaFuncAttributeMaxDynamicSharedMemorySize, GS_N4);
    cudaFuncSetAttribute((const void*)gemm_h<false,false,4,2,false>, cudaFuncAttributeMaxDynamicSharedMemorySize, GS_N4);
    cudaFuncSetAttribute((const void*)gemm_h<true,false,4,2,false>,  cudaFuncAttributeMaxDynamicSharedMemorySize, GS_T4);
    cudaFuncSetAttribute((const void*)gemm_h<false,true,2,3,false>,  cudaFuncAttributeMaxDynamicSharedMemorySize, GS_N2);
    cudaFuncSetAttribute((const void*)gemm_h<false,false,2,3,true>,  cudaFuncAttributeMaxDynamicSharedMemorySize, GS_N2);

    detect_mask_k<<<1,256>>>((const unsigned int*)mask);

    { // float -> half: q,k,v + Wq,Wk,Wv,Wfc,Wc
        ConvP cp{};
        cp.src[0]=q;   cp.dst[0]=qch;  cp.n[0]=NQ;
        cp.src[1]=k;   cp.dst[1]=kch;  cp.n[1]=NQ;
        cp.src[2]=v;   cp.dst[2]=vch;  cp.n[2]=NQ;
        cp.src[3]=Wq;  cp.dst[3]=Wqh;  cp.n[3]=NW;
        cp.src[4]=Wk;  cp.dst[4]=Wkh;  cp.n[4]=NW;
        cp.src[5]=Wv;  cp.dst[5]=Wvh;  cp.n[5]=NW;
        cp.src[6]=Wfc; cp.dst[6]=Wfch; cp.n[6]=NW;
        cp.src[7]=Wc;  cp.dst[7]=Wch;  cp.n[7]=D_*72;
        conv_k<<<dim3(NQ/1024, 8), 256>>>(cp);
    }
    add_txt_k<<<(NQ + 255)/256, 256>>>(q, txt);

    { // Q/K/V projections -> half (BN=128)
        GemmHP g{};
        g.A[0]=qch; g.A[1]=kch; g.A[2]=vch;
        g.Bw[0]=Wqh; g.Bw[1]=Wkh; g.Bw[2]=Wvh;
        g.bias[0]=bq; g.bias[1]=bk; g.bias[2]=bv;
        g.C[0]=qhh; g.C[1]=khh; g.C[2]=vhh;
        g.N=D_; g.K=D_; g.lda=D_; g.ldb=D_; g.ldc=D_;
        g.nSets=3; g.Hp=1; g.alpha=1.f;
        gemm_h<false,true,4,2,false><<<dim3(M/128, D_/128, 3), 128, GS_N4>>>(g);
    }
    { // cond: qt(half) @ Wc(half) + bc -> sw fp32 (bounded N=72)
        GemmHP g{};
        g.A[0]=qth; g.Bw[0]=Wch; g.bias[0]=bc; g.C[0]=sw;
        g.N=72; g.K=D_; g.lda=D_; g.ldb=72; g.ldc=72;
        g.nSets=1; g.Hp=1; g.alpha=1.f;
        gemm_h<false,false,2,3,true><<<dim3(M/128, 2, 1), 128, GS_N2>>>(g);
    }
    { // S = 0.125 * Q @ K^T -> P fp32 (BN=128)
        GemmHP g{};
        g.A[0]=qhh; g.Bw[0]=khh; g.C[0]=P;
        g.N=L_; g.K=64; g.lda=D_; g.ldb=D_; g.ldc=L_;
        g.aSB=(long long)L_*D_; g.aSH=64;
        g.bSB=(long long)L_*D_; g.bSH=64;
        g.cSB=(long long)H_*L_*L_; g.cSH=(long long)L_*L_;
        g.nSets=1; g.Hp=H_; g.alpha=0.125f;
        gemm_h<true,false,4,2,false><<<dim3(L_/128, L_/128, B_*H_), 128, GS_T4>>>(g);
    }
    fuse_softmax_k<<<M, 384>>>(ploc, mask, P);
    { // ctx = P @ V -> half (BN=64)
        GemmHP g{};
        g.A[0]=Ph; g.Bw[0]=vhh; g.C[0]=ctxh;
        g.N=64; g.K=L_; g.lda=L_; g.ldb=D_; g.ldc=D_;
        g.aSB=(long long)H_*L_*L_; g.aSH=(long long)L_*L_;
        g.bSB=(long long)L_*D_; g.bSH=64;
        g.cSB=(long long)L_*D_; g.cSH=64;
        g.nSets=1; g.Hp=H_; g.alpha=1.f;
        gemm_h<false,true,2,3,false><<<dim3(L_/128, 1, B_*H_), 128, GS_N2>>>(g);
    }
    { // x = ctx @ Wfc + bfc + q (fp32 out, BN=128)
        GemmHP g{};
        g.A[0]=ctxh; g.Bw[0]=Wfch; g.bias[0]=bfc; g.C[0]=xx;
        g.resid=q; g.N=D_; g.K=D_; g.lda=D_; g.ldb=D_; g.ldc=D_;
        g.nSets=1; g.Hp=1; g.alpha=1.f;
        gemm_h<false,false,4,2,false><<<dim3(M/128, D_/128, 1), 128, GS_N4>>>(g);
    }
    ln_k<<<M, 256>>>(lns, lnb, y);
}